// round 13
// baseline (speedup 1.0000x reference)
#include <cuda_runtime.h>
#include <cuda_bf16.h>
#include <cuda_pipeline.h>
#include <mma.h>
#include <math.h>

using namespace nvcuda;

// Problem constants
#define B_  2
#define S_  2048
#define D_  1024
#define H_  16
#define DK_ 64
#define M_  (B_*S_)

// GEMM v2 tiling (measured ~105us per GEMM, 2 CTAs/SM)
#define BM 128
#define BN 128
#define BK 32
#define LDT 40
#define TILE_ELEMS (BM*LDT)
#define STAGE_ELEMS (4*TILE_ELEMS)
#define SMEM_BYTES (2*STAGE_ELEMS*2)

// Flash v6 smem layout (bytes): 64 queries, DOUBLE-buffered KV, P aliased on S.
// Q hi/lo 18432 + KV x2 73728 + S/P 18432 + stats 768 = 111360 -> 2 CTAs/SM.
#define FQH 0
#define FQL 9216
#define FKV0 18432           // Kh,Kl,Vh,Vl each 9216 -> ends 55296
#define FKV1 55296           // -> ends 92160
#define FS  92160            // 64 x 72 f32 (S) ALIASED with P hi/lo bf16 stride 144
#define FST 110592           // m[64], l[64], sc[64]
#define FLASH_SMEM 111360

// Scratch (device globals — no allocation allowed)
__device__ __nv_bfloat16 g_Xh[M_*D_];
__device__ __nv_bfloat16 g_Xl[M_*D_];
__device__ __nv_bfloat16 g_Wh[D_*D_];
__device__ __nv_bfloat16 g_Wl[D_*D_];
__device__ __nv_bfloat16 g_Qh[M_*D_];
__device__ __nv_bfloat16 g_Ql[M_*D_];
__device__ __nv_bfloat16 g_Kh[M_*D_];
__device__ __nv_bfloat16 g_Kl[M_*D_];
__device__ __nv_bfloat16 g_Vh[M_*D_];
__device__ __nv_bfloat16 g_Vl[M_*D_];

// ---------------------------------------------------------------------------
// fp32 -> (hi, lo) bf16 split helpers.
// ---------------------------------------------------------------------------
__device__ __forceinline__ void split4(const float4* src, __nv_bfloat16* hi,
                                       __nv_bfloat16* lo, int i)
{
    float4 v = src[i];
    __nv_bfloat16 h0 = __float2bfloat16(v.x);
    __nv_bfloat16 h1 = __float2bfloat16(v.y);
    __nv_bfloat16 h2 = __float2bfloat16(v.z);
    __nv_bfloat16 h3 = __float2bfloat16(v.w);
    __nv_bfloat162 hh0, hh1, ll0, ll1;
    hh0.x = h0; hh0.y = h1; hh1.x = h2; hh1.y = h3;
    ll0.x = __float2bfloat16(v.x - __bfloat162float(h0));
    ll0.y = __float2bfloat16(v.y - __bfloat162float(h1));
    ll1.x = __float2bfloat16(v.z - __bfloat162float(h2));
    ll1.y = __float2bfloat16(v.w - __bfloat162float(h3));
    *(__nv_bfloat162*)&hi[i*4]     = hh0;
    *(__nv_bfloat162*)&hi[i*4 + 2] = hh1;
    *(__nv_bfloat162*)&lo[i*4]     = ll0;
    *(__nv_bfloat162*)&lo[i*4 + 2] = ll1;
}

__global__ __launch_bounds__(256)
void cvt_merged_kernel(const float4* __restrict__ x,
                       __nv_bfloat16* __restrict__ xh,
                       __nv_bfloat16* __restrict__ xl,
                       int nx4,
                       const float4* __restrict__ w,
                       __nv_bfloat16* __restrict__ wh,
                       __nv_bfloat16* __restrict__ wl,
                       int nw4)
{
    int i = blockIdx.x * blockDim.x + threadIdx.x;
    if (i < nx4) {
        split4(x, xh, xl, i);
    } else if (i < nx4 + nw4) {
        split4(w, wh, wl, i - nx4);
    }
}

// ---------------------------------------------------------------------------
// GEMM v2 + optional split epilogue (unchanged from R12).
// ---------------------------------------------------------------------------
__global__ __launch_bounds__(256)
void gemm_wmma_kernel(const __nv_bfloat16* __restrict__ Xh,
                      const __nv_bfloat16* __restrict__ Xl,
                      const __nv_bfloat16* __restrict__ Wh,
                      const __nv_bfloat16* __restrict__ Wl,
                      const float* __restrict__ bias,
                      float* __restrict__ Y,
                      __nv_bfloat16* __restrict__ Yh,
                      __nv_bfloat16* __restrict__ Yl,
                      int split,
                      int M, int N, int K)
{
    extern __shared__ __nv_bfloat16 sm[];
    __shared__ __align__(16) float biasTile[16][136];

    const int tid = threadIdx.x;
    const int wid = tid >> 5;
    const int m0  = blockIdx.y * BM;
    const int n0  = blockIdx.x * BN;
    const int wm  = (wid & 1) * 64;
    const int wn  = (wid >> 1) * 32;

    for (int idx = tid; idx < 16 * 128; idx += 256) {
        int r = idx >> 7;
        int c = idx & 127;
        biasTile[r][c] = bias[n0 + c];
    }
    __syncthreads();

    wmma::fragment<wmma::accumulator, 16, 16, 16, float> acc[4][2];
    for (int mi = 0; mi < 4; mi++)
        for (int ni = 0; ni < 2; ni++)
            wmma::load_matrix_sync(acc[mi][ni], &biasTile[0][wn + ni * 16], 136,
                                   wmma::mem_row_major);

    const int NT = K / BK;

    {
        for (int p = 0; p < 2; p++) {
            int chunk = tid + p * 256;
            int row = chunk >> 2;
            int cc  = chunk & 3;
            const __nv_bfloat16* sa = Xh + (size_t)(m0 + row) * K + cc * 8;
            const __nv_bfloat16* sb = Xl + (size_t)(m0 + row) * K + cc * 8;
            const __nv_bfloat16* sc = Wh + (size_t)(n0 + row) * K + cc * 8;
            const __nv_bfloat16* sd = Wl + (size_t)(n0 + row) * K + cc * 8;
            int so = row * LDT + cc * 8;
            __pipeline_memcpy_async(&sm[so], sa, 16);
            __pipeline_memcpy_async(&sm[TILE_ELEMS + so], sb, 16);
            __pipeline_memcpy_async(&sm[2 * TILE_ELEMS + so], sc, 16);
            __pipeline_memcpy_async(&sm[3 * TILE_ELEMS + so], sd, 16);
        }
        __pipeline_commit();
    }

    for (int t = 0; t < NT; t++) {
        int st = (t & 1) * STAGE_ELEMS;
        if (t + 1 < NT) {
            int k0 = (t + 1) * BK;
            int sn = ((t + 1) & 1) * STAGE_ELEMS;
            for (int p = 0; p < 2; p++) {
                int chunk = tid + p * 256;
                int row = chunk >> 2;
                int cc  = chunk & 3;
                const __nv_bfloat16* sa = Xh + (size_t)(m0 + row) * K + k0 + cc * 8;
                const __nv_bfloat16* sb = Xl + (size_t)(m0 + row) * K + k0 + cc * 8;
                const __nv_bfloat16* sc = Wh + (size_t)(n0 + row) * K + k0 + cc * 8;
                const __nv_bfloat16* sd = Wl + (size_t)(n0 + row) * K + k0 + cc * 8;
                int so = row * LDT + cc * 8;
                __pipeline_memcpy_async(&sm[sn + so], sa, 16);
                __pipeline_memcpy_async(&sm[sn + TILE_ELEMS + so], sb, 16);
                __pipeline_memcpy_async(&sm[sn + 2 * TILE_ELEMS + so], sc, 16);
                __pipeline_memcpy_async(&sm[sn + 3 * TILE_ELEMS + so], sd, 16);
            }
            __pipeline_commit();
            __pipeline_wait_prior(1);
        } else {
            __pipeline_wait_prior(0);
        }
        __syncthreads();

        for (int ks = 0; ks < 2; ks++) {
            int kc = ks * 16;
            wmma::fragment<wmma::matrix_a, 16, 16, 16, __nv_bfloat16, wmma::row_major> ah[4], al[4];
            wmma::fragment<wmma::matrix_b, 16, 16, 16, __nv_bfloat16, wmma::col_major> bh[2], bl[2];
            for (int mi = 0; mi < 4; mi++) {
                int r = wm + mi * 16;
                wmma::load_matrix_sync(ah[mi], &sm[st + r * LDT + kc], LDT);
                wmma::load_matrix_sync(al[mi], &sm[st + TILE_ELEMS + r * LDT + kc], LDT);
            }
            for (int ni = 0; ni < 2; ni++) {
                int r = wn + ni * 16;
                wmma::load_matrix_sync(bh[ni], &sm[st + 2 * TILE_ELEMS + r * LDT + kc], LDT);
                wmma::load_matrix_sync(bl[ni], &sm[st + 3 * TILE_ELEMS + r * LDT + kc], LDT);
            }
            for (int mi = 0; mi < 4; mi++) {
                for (int ni = 0; ni < 2; ni++) {
                    wmma::mma_sync(acc[mi][ni], ah[mi], bh[ni], acc[mi][ni]);
                    wmma::mma_sync(acc[mi][ni], ah[mi], bl[ni], acc[mi][ni]);
                    wmma::mma_sync(acc[mi][ni], al[mi], bh[ni], acc[mi][ni]);
                }
            }
        }
        __syncthreads();
    }

    if (split == 0) {
        for (int mi = 0; mi < 4; mi++) {
            for (int ni = 0; ni < 2; ni++) {
                int row = m0 + wm + mi * 16;
                int col = n0 + wn + ni * 16;
                wmma::store_matrix_sync(&Y[(size_t)row * N + col], acc[mi][ni], N,
                                        wmma::mem_row_major);
            }
        }
    } else {
        float* stage = (float*)sm;
        for (int mi = 0; mi < 4; mi++)
            for (int ni = 0; ni < 2; ni++)
                wmma::store_matrix_sync(stage + (wm + mi * 16) * 132 + wn + ni * 16,
                                        acc[mi][ni], 132, wmma::mem_row_major);
        __syncthreads();
        for (int idx = tid; idx < 128 * 128; idx += 256) {
            int r = idx >> 7;
            int c = idx & 127;
            float v = stage[r * 132 + c];
            __nv_bfloat16 hv = __float2bfloat16(v);
            size_t g = (size_t)(m0 + r) * N + n0 + c;
            Yh[g] = hv;
            Yl[g] = __float2bfloat16(v - __bfloat162float(hv));
        }
    }
}

// ---------------------------------------------------------------------------
// Flash v6 (causal, tensor-core): 64 queries/CTA, DOUBLE-buffered KV,
// P aliased onto S (row-disjoint, read-before-write within warp),
// register O accumulators. ~111KB smem -> 2 CTAs/SM, loads fully overlapped.
// ---------------------------------------------------------------------------
__device__ __forceinline__ void flash_load_64(char* dst, const __nv_bfloat16* src,
                                              int rowbase, int h, int tid)
{
    for (int p = 0; p < 2; p++) {
        int idx = tid + p * 256;     // 0..511
        int r = idx >> 3;            // 0..63
        int c = idx & 7;
        const __nv_bfloat16* s = src + (size_t)(rowbase + r) * D_ + h * DK_ + c * 8;
        __pipeline_memcpy_async(dst + r * 144 + c * 16, s, 16);
    }
}

__device__ __forceinline__ void flash_load_kv(char* kv,
                                              const __nv_bfloat16* Kh_g,
                                              const __nv_bfloat16* Kl_g,
                                              const __nv_bfloat16* Vh_g,
                                              const __nv_bfloat16* Vl_g,
                                              int rowbase, int h, int tid)
{
    flash_load_64(kv,         Kh_g, rowbase, h, tid);
    flash_load_64(kv + 9216,  Kl_g, rowbase, h, tid);
    flash_load_64(kv + 18432, Vh_g, rowbase, h, tid);
    flash_load_64(kv + 27648, Vl_g, rowbase, h, tid);
}

// Scale f32 accumulator fragment rows (sm_80+ layout, validated R11):
// elements {0,1,4,5} -> row lane/4, {2,3,6,7} -> row lane/4 + 8.
__device__ __forceinline__ void scale_frag_rows(
    wmma::fragment<wmma::accumulator, 16, 16, 16, float>& f, float s0, float s1)
{
    f.x[0] *= s0; f.x[1] *= s0; f.x[4] *= s0; f.x[5] *= s0;
    f.x[2] *= s1; f.x[3] *= s1; f.x[6] *= s1; f.x[7] *= s1;
}

__global__ __launch_bounds__(256)
void flash_wmma_kernel(const __nv_bfloat16* __restrict__ Qh_g,
                       const __nv_bfloat16* __restrict__ Ql_g,
                       const __nv_bfloat16* __restrict__ Kh_g,
                       const __nv_bfloat16* __restrict__ Kl_g,
                       const __nv_bfloat16* __restrict__ Vh_g,
                       const __nv_bfloat16* __restrict__ Vl_g,
                       __nv_bfloat16* __restrict__ Oh_g,
                       __nv_bfloat16* __restrict__ Ol_g)
{
    extern __shared__ char smb[];

    const int tid  = threadIdx.x;
    const int wid  = tid >> 5;
    const int lane = tid & 31;
    const int qt   = blockIdx.x;          // 0..31
    const int bhv  = blockIdx.y;          // 0..31
    const int b    = bhv / H_;
    const int h    = bhv % H_;
    const int q0   = qt * 64;

    float* Sbuf  = (float*)(smb + FS);                 // 64 x 72 f32
    __nv_bfloat16* Pbuf = (__nv_bfloat16*)(smb + FS);  // aliased: stride 144,
                                                       // hi at +0..63, lo at +72..135
    float* mArr  = (float*)(smb + FST);
    float* lArr  = mArr + 64;
    float* scArr = lArr + 64;

    // Prologue: Q (hi/lo) + KV tile 0 in one group.
    flash_load_64(smb + FQH, Qh_g, b * S_ + q0, h, tid);
    flash_load_64(smb + FQL, Ql_g, b * S_ + q0, h, tid);
    flash_load_kv(smb + FKV0, Kh_g, Kl_g, Vh_g, Vl_g, b * S_, h, tid);
    __pipeline_commit();

    if (tid < 64) {
        mArr[tid] = -INFINITY;
        lArr[tid] = 0.f;
    }

    const int qr   = (wid & 3) * 16;      // warp q-row base
    const int dc   = (wid >> 2) * 32;     // warp key/dim base
    const int rowA = qr + (lane >> 2);
    const int rowB = rowA + 8;

    wmma::fragment<wmma::accumulator, 16, 16, 16, float> o[2];
    wmma::fill_fragment(o[0], 0.f);
    wmma::fill_fragment(o[1], 0.f);

    const __nv_bfloat16* Qhs = (const __nv_bfloat16*)(smb + FQH);
    const __nv_bfloat16* Qls = (const __nv_bfloat16*)(smb + FQL);

    const int ntiles = qt + 1;
    for (int kt = 0; kt < ntiles; kt++) {
        __syncthreads();                 // (A) everyone done with iter kt-1
        if (kt + 1 < ntiles) {
            // buffer (kt+1)&1 last read in iter kt-1; safe after sync (A)
            flash_load_kv(smb + (((kt + 1) & 1) ? FKV1 : FKV0),
                          Kh_g, Kl_g, Vh_g, Vl_g, b * S_ + (kt + 1) * 64, h, tid);
            __pipeline_commit();
            __pipeline_wait_prior(1);    // KV(kt) group done
        } else {
            __pipeline_wait_prior(0);
        }
        __syncthreads();                 // (B) KV tile kt visible to all

        const char* kv = smb + ((kt & 1) ? FKV1 : FKV0);
        const __nv_bfloat16* Khs = (const __nv_bfloat16*)kv;
        const __nv_bfloat16* Kls = (const __nv_bfloat16*)(kv + 9216);
        const __nv_bfloat16* Vhs = (const __nv_bfloat16*)(kv + 18432);
        const __nv_bfloat16* Vls = (const __nv_bfloat16*)(kv + 27648);

        // ---- S = Q K^T : warp -> 16 q-rows x 32 keys ----
        {
            wmma::fragment<wmma::accumulator, 16, 16, 16, float> s[2];
            wmma::fill_fragment(s[0], 0.f);
            wmma::fill_fragment(s[1], 0.f);
            for (int ks = 0; ks < 4; ks++) {
                int kc = ks * 16;
                wmma::fragment<wmma::matrix_a, 16, 16, 16, __nv_bfloat16, wmma::row_major> qh, ql;
                wmma::load_matrix_sync(qh, Qhs + qr * 72 + kc, 72);
                wmma::load_matrix_sync(ql, Qls + qr * 72 + kc, 72);
                for (int ni = 0; ni < 2; ni++) {
                    wmma::fragment<wmma::matrix_b, 16, 16, 16, __nv_bfloat16, wmma::col_major> kh, kl;
                    wmma::load_matrix_sync(kh, Khs + (dc + ni * 16) * 72 + kc, 72);
                    wmma::load_matrix_sync(kl, Kls + (dc + ni * 16) * 72 + kc, 72);
                    wmma::mma_sync(s[ni], qh, kh, s[ni]);
                    wmma::mma_sync(s[ni], qh, kl, s[ni]);
                    wmma::mma_sync(s[ni], ql, kh, s[ni]);
                }
            }
            wmma::store_matrix_sync(Sbuf + qr * 72 + dc,      s[0], 72, wmma::mem_row_major);
            wmma::store_matrix_sync(Sbuf + qr * 72 + dc + 16, s[1], 72, wmma::mem_row_major);
        }
        __syncthreads();                 // (C)

        // ---- online softmax: 4 threads/row, 16 cols each; P overwrites S ----
        {
            const int r  = tid >> 2;
            const int sub = tid & 3;
            const int cb = sub * 16;
            const int kb = kt * 64;
            float* Srow = Sbuf + r * 72 + cb;
            float vals[16];
            float mx = -INFINITY;
            for (int i = 0; i < 16; i++) {
                float v = Srow[i] * 0.125f;
                if (kb + cb + i > q0 + r) v = -1e9f;
                vals[i] = v;
                mx = fmaxf(mx, v);
            }
            mx = fmaxf(mx, __shfl_xor_sync(0xffffffffu, mx, 1));
            mx = fmaxf(mx, __shfl_xor_sync(0xffffffffu, mx, 2));
            float mold = mArr[r];
            float mnew = fmaxf(mold, mx);
            float sum = 0.f;
            // P hi at Pbuf[r*144 + c], P lo at Pbuf[r*144 + 72 + c] (c in [0,64)).
            // All lanes of this warp finished their S reads (vals[]) before the
            // warp's stores issue (program order), and rows are warp-disjoint.
            __nv_bfloat16* Ph = Pbuf + r * 144;
            __nv_bfloat16* Pl = Ph + 72;
            for (int i = 0; i < 16; i += 2) {
                float p0 = __expf(vals[i] - mnew);
                float p1 = __expf(vals[i + 1] - mnew);
                sum += p0 + p1;
                __nv_bfloat16 h0 = __float2bfloat16(p0);
                __nv_bfloat16 h1 = __float2bfloat16(p1);
                __nv_bfloat162 hh, ll;
                hh.x = h0; hh.y = h1;
                ll.x = __float2bfloat16(p0 - __bfloat162float(h0));
                ll.y = __float2bfloat16(p1 - __bfloat162float(h1));
                *(__nv_bfloat162*)&Ph[cb + i] = hh;
                *(__nv_bfloat162*)&Pl[cb + i] = ll;
            }
            sum += __shfl_xor_sync(0xffffffffu, sum, 1);
            sum += __shfl_xor_sync(0xffffffffu, sum, 2);
            float sc = __expf(mold - mnew);
            if (sub == 0) {
                mArr[r] = mnew;
                lArr[r] = lArr[r] * sc + sum;
                scArr[r] = sc;
            }
        }
        __syncthreads();                 // (D)

        // ---- rescale O in registers, then O += P V (warp: 16 rows x 32 dims) ----
        {
            float s0 = scArr[rowA];
            float s1 = scArr[rowB];
            scale_frag_rows(o[0], s0, s1);
            scale_frag_rows(o[1], s0, s1);
            for (int ks = 0; ks < 4; ks++) {
                int kc = ks * 16;
                wmma::fragment<wmma::matrix_a, 16, 16, 16, __nv_bfloat16, wmma::row_major> ph, pl;
                wmma::load_matrix_sync(ph, Pbuf + qr * 144 + kc, 144);
                wmma::load_matrix_sync(pl, Pbuf + qr * 144 + 72 + kc, 144);
                for (int ni = 0; ni < 2; ni++) {
                    wmma::fragment<wmma::matrix_b, 16, 16, 16, __nv_bfloat16, wmma::row_major> vh, vl;
                    wmma::load_matrix_sync(vh, Vhs + kc * 72 + dc + ni * 16, 72);
                    wmma::load_matrix_sync(vl, Vls + kc * 72 + dc + ni * 16, 72);
                    wmma::mma_sync(o[ni], ph, vh, o[ni]);
                    wmma::mma_sync(o[ni], ph, vl, o[ni]);
                    wmma::mma_sync(o[ni], pl, vh, o[ni]);
                }
            }
        }
    }

    // ---- epilogue: normalize, stage to smem, split to hi/lo bf16 global ----
    __syncthreads();                     // P region dead; reuse as staging
    {
        float i0 = 1.f / lArr[rowA];
        float i1 = 1.f / lArr[rowB];
        scale_frag_rows(o[0], i0, i1);
        scale_frag_rows(o[1], i0, i1);
        wmma::store_matrix_sync(Sbuf + qr * 72 + dc,      o[0], 72, wmma::mem_row_major);
        wmma::store_matrix_sync(Sbuf + qr * 72 + dc + 16, o[1], 72, wmma::mem_row_major);
    }
    __syncthreads();
    for (int idx = tid; idx < 64 * 64; idx += 256) {
        int r = idx >> 6;
        int c = idx & 63;
        float v = Sbuf[r * 72 + c];
        __nv_bfloat16 hv = __float2bfloat16(v);
        size_t g = (size_t)(b * S_ + q0 + r) * D_ + h * DK_ + c;
        Oh_g[g] = hv;
        Ol_g[g] = __float2bfloat16(v - __bfloat162float(hv));
    }
}

// ---------------------------------------------------------------------------
// Launch. Inputs: q,k,v,mask,Wq,bq,Wk,bk,Wv,bv,Wo,bo
// ---------------------------------------------------------------------------
extern "C" void kernel_launch(void* const* d_in, const int* in_sizes, int n_in,
                              void* d_out, int out_size)
{
    const float* q    = (const float*)d_in[0];
    const float* k    = (const float*)d_in[1];
    const float* v    = (const float*)d_in[2];
    const float* Wq   = (const float*)d_in[4];
    const float* bq   = (const float*)d_in[5];
    const float* Wk   = (const float*)d_in[6];
    const float* bk   = (const float*)d_in[7];
    const float* Wv   = (const float*)d_in[8];
    const float* bv   = (const float*)d_in[9];
    const float* Wo   = (const float*)d_in[10];
    const float* bo   = (const float*)d_in[11];
    float* out = (float*)d_out;

    __nv_bfloat16 *Xh; __nv_bfloat16 *Xl; __nv_bfloat16 *Wh; __nv_bfloat16 *Wl;
    __nv_bfloat16 *Qh; __nv_bfloat16 *Ql; __nv_bfloat16 *Kh; __nv_bfloat16 *Kl;
    __nv_bfloat16 *Vh; __nv_bfloat16 *Vl;
    cudaGetSymbolAddress((void**)&Xh, g_Xh);
    cudaGetSymbolAddress((void**)&Xl, g_Xl);
    cudaGetSymbolAddress((void**)&Wh, g_Wh);
    cudaGetSymbolAddress((void**)&Wl, g_Wl);
    cudaGetSymbolAddress((void**)&Qh, g_Qh);
    cudaGetSymbolAddress((void**)&Ql, g_Ql);
    cudaGetSymbolAddress((void**)&Kh, g_Kh);
    cudaGetSymbolAddress((void**)&Kl, g_Kl);
    cudaGetSymbolAddress((void**)&Vh, g_Vh);
    cudaGetSymbolAddress((void**)&Vl, g_Vl);

    cudaFuncSetAttribute(gemm_wmma_kernel,
                         cudaFuncAttributeMaxDynamicSharedMemorySize, SMEM_BYTES);
    cudaFuncSetAttribute(flash_wmma_kernel,
                         cudaFuncAttributeMaxDynamicSharedMemorySize, FLASH_SMEM);

    const int nX4 = M_ * D_ / 4;
    const int nW4 = D_ * D_ / 4;
    dim3 cvtg((nX4 + nW4 + 255) / 256);
    dim3 cvtw((nW4 + 255) / 256);
    dim3 ggrid(D_ / BN, M_ / BM);

    // Projections: GEMM writes hi/lo bf16 directly.
    cvt_merged_kernel<<<cvtg, 256>>>((const float4*)q, Xh, Xl, nX4,
                                     (const float4*)Wq, Wh, Wl, nW4);
    gemm_wmma_kernel<<<ggrid, 256, SMEM_BYTES>>>(Xh, Xl, Wh, Wl, bq, out,
                                                 Qh, Ql, 1, M_, D_, D_);
    cvt_merged_kernel<<<cvtg, 256>>>((const float4*)k, Xh, Xl, nX4,
                                     (const float4*)Wk, Wh, Wl, nW4);
    gemm_wmma_kernel<<<ggrid, 256, SMEM_BYTES>>>(Xh, Xl, Wh, Wl, bk, out,
                                                 Kh, Kl, 1, M_, D_, D_);
    cvt_merged_kernel<<<cvtg, 256>>>((const float4*)v, Xh, Xl, nX4,
                                     (const float4*)Wv, Wh, Wl, nW4);
    gemm_wmma_kernel<<<ggrid, 256, SMEM_BYTES>>>(Xh, Xl, Wh, Wl, bv, out,
                                                 Vh, Vl, 1, M_, D_, D_);

    // Attention: writes O hi/lo into g_Xh/g_Xl (input of the final GEMM).
    dim3 fgrid(S_ / 64, B_ * H_);   // (32, 32)
    flash_wmma_kernel<<<fgrid, 256, FLASH_SMEM>>>(Qh, Ql, Kh, Kl, Vh, Vl, Xh, Xl);

    // Output projection: W-only convert, fp32 output.
    cvt_merged_kernel<<<cvtw, 256>>>((const float4*)q, Xh, Xl, 0,
                                     (const float4*)Wo, Wh, Wl, nW4);
    gemm_wmma_kernel<<<ggrid, 256, SMEM_BYTES>>>(Xh, Xl, Wh, Wl, bo, out,
                                                 Qh, Ql, 0, M_, D_, D_);
}

// round 14
// speedup vs baseline: 1.0084x; 1.0084x over previous
#include <cuda_runtime.h>
#include <cuda_bf16.h>
#include <cuda_pipeline.h>
#include <mma.h>
#include <math.h>

using namespace nvcuda;

// Problem constants
#define B_  2
#define S_  2048
#define D_  1024
#define H_  16
#define DK_ 64
#define M_  (B_*S_)

// GEMM tiling (measured ~105us per GEMM, 2 CTAs/SM)
#define BM 128
#define BN 128
#define BK 32
#define LDT 40
#define TILE_ELEMS (BM*LDT)
#define STAGE_ELEMS (4*TILE_ELEMS)
#define SMEM_BYTES (2*STAGE_ELEMS*2)

// Flash v7 smem (bytes): 64 queries, double-buffered KV, P aliased on S, 3 syncs.
#define FQH 0
#define FQL 9216
#define FKV0 18432
#define FKV1 55296
#define FS  92160
#define FST 110592
#define FLASH_SMEM 111360

// Scratch (device globals — no allocation allowed)
__device__ __nv_bfloat16 g_X1h[M_*D_];
__device__ __nv_bfloat16 g_X1l[M_*D_];
__device__ __nv_bfloat16 g_X2h[M_*D_];
__device__ __nv_bfloat16 g_X2l[M_*D_];
__device__ __nv_bfloat16 g_X3h[M_*D_];
__device__ __nv_bfloat16 g_X3l[M_*D_];
__device__ __nv_bfloat16 g_W1h[D_*D_];
__device__ __nv_bfloat16 g_W1l[D_*D_];
__device__ __nv_bfloat16 g_W2h[D_*D_];
__device__ __nv_bfloat16 g_W2l[D_*D_];
__device__ __nv_bfloat16 g_W3h[D_*D_];
__device__ __nv_bfloat16 g_W3l[D_*D_];
__device__ __nv_bfloat16 g_Qh[M_*D_];
__device__ __nv_bfloat16 g_Ql[M_*D_];
__device__ __nv_bfloat16 g_Kh[M_*D_];
__device__ __nv_bfloat16 g_Kl[M_*D_];
__device__ __nv_bfloat16 g_Vh[M_*D_];
__device__ __nv_bfloat16 g_Vl[M_*D_];

struct GemmSet {
    const __nv_bfloat16* Xh;
    const __nv_bfloat16* Xl;
    const __nv_bfloat16* Wh;
    const __nv_bfloat16* Wl;
    const float* bias;
    float* Y;
    __nv_bfloat16* Yh;
    __nv_bfloat16* Yl;
    int split;
};

// ---------------------------------------------------------------------------
// fp32 -> (hi, lo) bf16 split helpers.
// ---------------------------------------------------------------------------
__device__ __forceinline__ void split4(const float4* src, __nv_bfloat16* hi,
                                       __nv_bfloat16* lo, int i)
{
    float4 v = src[i];
    __nv_bfloat16 h0 = __float2bfloat16(v.x);
    __nv_bfloat16 h1 = __float2bfloat16(v.y);
    __nv_bfloat16 h2 = __float2bfloat16(v.z);
    __nv_bfloat16 h3 = __float2bfloat16(v.w);
    __nv_bfloat162 hh0, hh1, ll0, ll1;
    hh0.x = h0; hh0.y = h1; hh1.x = h2; hh1.y = h3;
    ll0.x = __float2bfloat16(v.x - __bfloat162float(h0));
    ll0.y = __float2bfloat16(v.y - __bfloat162float(h1));
    ll1.x = __float2bfloat16(v.z - __bfloat162float(h2));
    ll1.y = __float2bfloat16(v.w - __bfloat162float(h3));
    *(__nv_bfloat162*)&hi[i*4]     = hh0;
    *(__nv_bfloat162*)&hi[i*4 + 2] = hh1;
    *(__nv_bfloat162*)&lo[i*4]     = ll0;
    *(__nv_bfloat162*)&lo[i*4 + 2] = ll1;
}

__global__ __launch_bounds__(256)
void cvt_merged_kernel(const float4* __restrict__ x,
                       __nv_bfloat16* __restrict__ xh,
                       __nv_bfloat16* __restrict__ xl,
                       int nx4,
                       const float4* __restrict__ w,
                       __nv_bfloat16* __restrict__ wh,
                       __nv_bfloat16* __restrict__ wl,
                       int nw4)
{
    int i = blockIdx.x * blockDim.x + threadIdx.x;
    if (i < nx4) {
        split4(x, xh, xl, i);
    } else if (i < nx4 + nw4) {
        split4(w, wh, wl, i - nx4);
    }
}

// ---------------------------------------------------------------------------
// Fused GEMM: grid.y selects one of up to 3 (X,W,bias,Y) sets (blockIdx.y>>5).
// Body identical to the measured-best v2 kernel.
// ---------------------------------------------------------------------------
__global__ __launch_bounds__(256)
void gemm_wmma_kernel(GemmSet s0, GemmSet s1, GemmSet s2, int N, int K)
{
    extern __shared__ __nv_bfloat16 sm[];
    __shared__ __align__(16) float biasTile[16][136];

    const int tid = threadIdx.x;
    const int wid = tid >> 5;
    const int sel = blockIdx.y >> 5;
    const GemmSet& s = (sel == 0) ? s0 : ((sel == 1) ? s1 : s2);
    const __nv_bfloat16* Xh = s.Xh;
    const __nv_bfloat16* Xl = s.Xl;
    const __nv_bfloat16* Wh = s.Wh;
    const __nv_bfloat16* Wl = s.Wl;

    const int m0  = (blockIdx.y & 31) * BM;
    const int n0  = blockIdx.x * BN;
    const int wm  = (wid & 1) * 64;
    const int wn  = (wid >> 1) * 32;

    for (int idx = tid; idx < 16 * 128; idx += 256) {
        int r = idx >> 7;
        int c = idx & 127;
        biasTile[r][c] = s.bias[n0 + c];
    }
    __syncthreads();

    wmma::fragment<wmma::accumulator, 16, 16, 16, float> acc[4][2];
    for (int mi = 0; mi < 4; mi++)
        for (int ni = 0; ni < 2; ni++)
            wmma::load_matrix_sync(acc[mi][ni], &biasTile[0][wn + ni * 16], 136,
                                   wmma::mem_row_major);

    const int NT = K / BK;

    {
        for (int p = 0; p < 2; p++) {
            int chunk = tid + p * 256;
            int row = chunk >> 2;
            int cc  = chunk & 3;
            const __nv_bfloat16* sa = Xh + (size_t)(m0 + row) * K + cc * 8;
            const __nv_bfloat16* sb = Xl + (size_t)(m0 + row) * K + cc * 8;
            const __nv_bfloat16* sc = Wh + (size_t)(n0 + row) * K + cc * 8;
            const __nv_bfloat16* sd = Wl + (size_t)(n0 + row) * K + cc * 8;
            int so = row * LDT + cc * 8;
            __pipeline_memcpy_async(&sm[so], sa, 16);
            __pipeline_memcpy_async(&sm[TILE_ELEMS + so], sb, 16);
            __pipeline_memcpy_async(&sm[2 * TILE_ELEMS + so], sc, 16);
            __pipeline_memcpy_async(&sm[3 * TILE_ELEMS + so], sd, 16);
        }
        __pipeline_commit();
    }

    for (int t = 0; t < NT; t++) {
        int st = (t & 1) * STAGE_ELEMS;
        if (t + 1 < NT) {
            int k0 = (t + 1) * BK;
            int sn = ((t + 1) & 1) * STAGE_ELEMS;
            for (int p = 0; p < 2; p++) {
                int chunk = tid + p * 256;
                int row = chunk >> 2;
                int cc  = chunk & 3;
                const __nv_bfloat16* sa = Xh + (size_t)(m0 + row) * K + k0 + cc * 8;
                const __nv_bfloat16* sb = Xl + (size_t)(m0 + row) * K + k0 + cc * 8;
                const __nv_bfloat16* sc = Wh + (size_t)(n0 + row) * K + k0 + cc * 8;
                const __nv_bfloat16* sd = Wl + (size_t)(n0 + row) * K + k0 + cc * 8;
                int so = row * LDT + cc * 8;
                __pipeline_memcpy_async(&sm[sn + so], sa, 16);
                __pipeline_memcpy_async(&sm[sn + TILE_ELEMS + so], sb, 16);
                __pipeline_memcpy_async(&sm[sn + 2 * TILE_ELEMS + so], sc, 16);
                __pipeline_memcpy_async(&sm[sn + 3 * TILE_ELEMS + so], sd, 16);
            }
            __pipeline_commit();
            __pipeline_wait_prior(1);
        } else {
            __pipeline_wait_prior(0);
        }
        __syncthreads();

        for (int ks = 0; ks < 2; ks++) {
            int kc = ks * 16;
            wmma::fragment<wmma::matrix_a, 16, 16, 16, __nv_bfloat16, wmma::row_major> ah[4], al[4];
            wmma::fragment<wmma::matrix_b, 16, 16, 16, __nv_bfloat16, wmma::col_major> bh[2], bl[2];
            for (int mi = 0; mi < 4; mi++) {
                int r = wm + mi * 16;
                wmma::load_matrix_sync(ah[mi], &sm[st + r * LDT + kc], LDT);
                wmma::load_matrix_sync(al[mi], &sm[st + TILE_ELEMS + r * LDT + kc], LDT);
            }
            for (int ni = 0; ni < 2; ni++) {
                int r = wn + ni * 16;
                wmma::load_matrix_sync(bh[ni], &sm[st + 2 * TILE_ELEMS + r * LDT + kc], LDT);
                wmma::load_matrix_sync(bl[ni], &sm[st + 3 * TILE_ELEMS + r * LDT + kc], LDT);
            }
            for (int mi = 0; mi < 4; mi++) {
                for (int ni = 0; ni < 2; ni++) {
                    wmma::mma_sync(acc[mi][ni], ah[mi], bh[ni], acc[mi][ni]);
                    wmma::mma_sync(acc[mi][ni], ah[mi], bl[ni], acc[mi][ni]);
                    wmma::mma_sync(acc[mi][ni], al[mi], bh[ni], acc[mi][ni]);
                }
            }
        }
        __syncthreads();
    }

    if (s.split == 0) {
        for (int mi = 0; mi < 4; mi++) {
            for (int ni = 0; ni < 2; ni++) {
                int row = m0 + wm + mi * 16;
                int col = n0 + wn + ni * 16;
                wmma::store_matrix_sync(&s.Y[(size_t)row * N + col], acc[mi][ni], N,
                                        wmma::mem_row_major);
            }
        }
    } else {
        float* stage = (float*)sm;
        for (int mi = 0; mi < 4; mi++)
            for (int ni = 0; ni < 2; ni++)
                wmma::store_matrix_sync(stage + (wm + mi * 16) * 132 + wn + ni * 16,
                                        acc[mi][ni], 132, wmma::mem_row_major);
        __syncthreads();
        for (int idx = tid; idx < 128 * 128; idx += 256) {
            int r = idx >> 7;
            int c = idx & 127;
            float v = stage[r * 132 + c];
            __nv_bfloat16 hv = __float2bfloat16(v);
            size_t g = (size_t)(m0 + r) * N + n0 + c;
            s.Yh[g] = hv;
            s.Yl[g] = __float2bfloat16(v - __bfloat162float(hv));
        }
    }
}

// ---------------------------------------------------------------------------
// Flash v7: v6 structure with 3 syncs/tile (prefetch issued after the
// top-of-iter barrier; target buffer's last reader was iter kt-1's PV).
// ---------------------------------------------------------------------------
__device__ __forceinline__ void flash_load_64(char* dst, const __nv_bfloat16* src,
                                              int rowbase, int h, int tid)
{
    for (int p = 0; p < 2; p++) {
        int idx = tid + p * 256;
        int r = idx >> 3;
        int c = idx & 7;
        const __nv_bfloat16* s = src + (size_t)(rowbase + r) * D_ + h * DK_ + c * 8;
        __pipeline_memcpy_async(dst + r * 144 + c * 16, s, 16);
    }
}

__device__ __forceinline__ void flash_load_kv(char* kv,
                                              const __nv_bfloat16* Kh_g,
                                              const __nv_bfloat16* Kl_g,
                                              const __nv_bfloat16* Vh_g,
                                              const __nv_bfloat16* Vl_g,
                                              int rowbase, int h, int tid)
{
    flash_load_64(kv,         Kh_g, rowbase, h, tid);
    flash_load_64(kv + 9216,  Kl_g, rowbase, h, tid);
    flash_load_64(kv + 18432, Vh_g, rowbase, h, tid);
    flash_load_64(kv + 27648, Vl_g, rowbase, h, tid);
}

__device__ __forceinline__ void scale_frag_rows(
    wmma::fragment<wmma::accumulator, 16, 16, 16, float>& f, float s0, float s1)
{
    f.x[0] *= s0; f.x[1] *= s0; f.x[4] *= s0; f.x[5] *= s0;
    f.x[2] *= s1; f.x[3] *= s1; f.x[6] *= s1; f.x[7] *= s1;
}

__global__ __launch_bounds__(256)
void flash_wmma_kernel(const __nv_bfloat16* __restrict__ Qh_g,
                       const __nv_bfloat16* __restrict__ Ql_g,
                       const __nv_bfloat16* __restrict__ Kh_g,
                       const __nv_bfloat16* __restrict__ Kl_g,
                       const __nv_bfloat16* __restrict__ Vh_g,
                       const __nv_bfloat16* __restrict__ Vl_g,
                       __nv_bfloat16* __restrict__ Oh_g,
                       __nv_bfloat16* __restrict__ Ol_g)
{
    extern __shared__ char smb[];

    const int tid  = threadIdx.x;
    const int wid  = tid >> 5;
    const int lane = tid & 31;
    const int qt   = blockIdx.x;
    const int bhv  = blockIdx.y;
    const int b    = bhv / H_;
    const int h    = bhv % H_;
    const int q0   = qt * 64;

    float* Sbuf  = (float*)(smb + FS);
    __nv_bfloat16* Pbuf = (__nv_bfloat16*)(smb + FS);
    float* mArr  = (float*)(smb + FST);
    float* lArr  = mArr + 64;
    float* scArr = lArr + 64;

    flash_load_64(smb + FQH, Qh_g, b * S_ + q0, h, tid);
    flash_load_64(smb + FQL, Ql_g, b * S_ + q0, h, tid);
    flash_load_kv(smb + FKV0, Kh_g, Kl_g, Vh_g, Vl_g, b * S_, h, tid);
    __pipeline_commit();

    if (tid < 64) {
        mArr[tid] = -INFINITY;
        lArr[tid] = 0.f;
    }

    const int qr   = (wid & 3) * 16;
    const int dc   = (wid >> 2) * 32;
    const int rowA = qr + (lane >> 2);
    const int rowB = rowA + 8;

    wmma::fragment<wmma::accumulator, 16, 16, 16, float> o[2];
    wmma::fill_fragment(o[0], 0.f);
    wmma::fill_fragment(o[1], 0.f);

    const __nv_bfloat16* Qhs = (const __nv_bfloat16*)(smb + FQH);
    const __nv_bfloat16* Qls = (const __nv_bfloat16*)(smb + FQL);

    const int ntiles = qt + 1;
    for (int kt = 0; kt < ntiles; kt++) {
        __pipeline_wait_prior(0);        // KV(kt) group done
        __syncthreads();                 // (B) visible to all; iter kt-1 retired
        if (kt + 1 < ntiles) {
            // target buffer's last reader finished in iter kt-1, before (B)
            flash_load_kv(smb + (((kt + 1) & 1) ? FKV1 : FKV0),
                          Kh_g, Kl_g, Vh_g, Vl_g, b * S_ + (kt + 1) * 64, h, tid);
            __pipeline_commit();
        }

        const char* kv = smb + ((kt & 1) ? FKV1 : FKV0);
        const __nv_bfloat16* Khs = (const __nv_bfloat16*)kv;
        const __nv_bfloat16* Kls = (const __nv_bfloat16*)(kv + 9216);
        const __nv_bfloat16* Vhs = (const __nv_bfloat16*)(kv + 18432);
        const __nv_bfloat16* Vls = (const __nv_bfloat16*)(kv + 27648);

        // ---- S = Q K^T ----
        {
            wmma::fragment<wmma::accumulator, 16, 16, 16, float> s[2];
            wmma::fill_fragment(s[0], 0.f);
            wmma::fill_fragment(s[1], 0.f);
            for (int ks = 0; ks < 4; ks++) {
                int kc = ks * 16;
                wmma::fragment<wmma::matrix_a, 16, 16, 16, __nv_bfloat16, wmma::row_major> qh, ql;
                wmma::load_matrix_sync(qh, Qhs + qr * 72 + kc, 72);
                wmma::load_matrix_sync(ql, Qls + qr * 72 + kc, 72);
                for (int ni = 0; ni < 2; ni++) {
                    wmma::fragment<wmma::matrix_b, 16, 16, 16, __nv_bfloat16, wmma::col_major> kh, kl;
                    wmma::load_matrix_sync(kh, Khs + (dc + ni * 16) * 72 + kc, 72);
                    wmma::load_matrix_sync(kl, Kls + (dc + ni * 16) * 72 + kc, 72);
                    wmma::mma_sync(s[ni], qh, kh, s[ni]);
                    wmma::mma_sync(s[ni], qh, kl, s[ni]);
                    wmma::mma_sync(s[ni], ql, kh, s[ni]);
                }
            }
            wmma::store_matrix_sync(Sbuf + qr * 72 + dc,      s[0], 72, wmma::mem_row_major);
            wmma::store_matrix_sync(Sbuf + qr * 72 + dc + 16, s[1], 72, wmma::mem_row_major);
        }
        __syncthreads();                 // (C)

        // ---- online softmax; P overwrites S (row-disjoint, read-before-write) ----
        {
            const int r  = tid >> 2;
            const int sub = tid & 3;
            const int cb = sub * 16;
            const int kb = kt * 64;
            float* Srow = Sbuf + r * 72 + cb;
            float vals[16];
            float mx = -INFINITY;
            for (int i = 0; i < 16; i++) {
                float v = Srow[i] * 0.125f;
                if (kb + cb + i > q0 + r) v = -1e9f;
                vals[i] = v;
                mx = fmaxf(mx, v);
            }
            mx = fmaxf(mx, __shfl_xor_sync(0xffffffffu, mx, 1));
            mx = fmaxf(mx, __shfl_xor_sync(0xffffffffu, mx, 2));
            float mold = mArr[r];
            float mnew = fmaxf(mold, mx);
            float sum = 0.f;
            __nv_bfloat16* Ph = Pbuf + r * 144;
            __nv_bfloat16* Pl = Ph + 72;
            for (int i = 0; i < 16; i += 2) {
                float p0 = __expf(vals[i] - mnew);
                float p1 = __expf(vals[i + 1] - mnew);
                sum += p0 + p1;
                __nv_bfloat16 h0 = __float2bfloat16(p0);
                __nv_bfloat16 h1 = __float2bfloat16(p1);
                __nv_bfloat162 hh, ll;
                hh.x = h0; hh.y = h1;
                ll.x = __float2bfloat16(p0 - __bfloat162float(h0));
                ll.y = __float2bfloat16(p1 - __bfloat162float(h1));
                *(__nv_bfloat162*)&Ph[cb + i] = hh;
                *(__nv_bfloat162*)&Pl[cb + i] = ll;
            }
            sum += __shfl_xor_sync(0xffffffffu, sum, 1);
            sum += __shfl_xor_sync(0xffffffffu, sum, 2);
            float sc = __expf(mold - mnew);
            if (sub == 0) {
                mArr[r] = mnew;
                lArr[r] = lArr[r] * sc + sum;
                scArr[r] = sc;
            }
        }
        __syncthreads();                 // (D)

        // ---- rescale O in registers, then O += P V ----
        {
            float s0 = scArr[rowA];
            float s1 = scArr[rowB];
            scale_frag_rows(o[0], s0, s1);
            scale_frag_rows(o[1], s0, s1);
            for (int ks = 0; ks < 4; ks++) {
                int kc = ks * 16;
                wmma::fragment<wmma::matrix_a, 16, 16, 16, __nv_bfloat16, wmma::row_major> ph, pl;
                wmma::load_matrix_sync(ph, Pbuf + qr * 144 + kc, 144);
                wmma::load_matrix_sync(pl, Pbuf + qr * 144 + 72 + kc, 144);
                for (int ni = 0; ni < 2; ni++) {
                    wmma::fragment<wmma::matrix_b, 16, 16, 16, __nv_bfloat16, wmma::row_major> vh, vl;
                    wmma::load_matrix_sync(vh, Vhs + kc * 72 + dc + ni * 16, 72);
                    wmma::load_matrix_sync(vl, Vls + kc * 72 + dc + ni * 16, 72);
                    wmma::mma_sync(o[ni], ph, vh, o[ni]);
                    wmma::mma_sync(o[ni], ph, vl, o[ni]);
                    wmma::mma_sync(o[ni], pl, vh, o[ni]);
                }
            }
        }
    }

    // ---- epilogue ----
    __syncthreads();
    {
        float i0 = 1.f / lArr[rowA];
        float i1 = 1.f / lArr[rowB];
        scale_frag_rows(o[0], i0, i1);
        scale_frag_rows(o[1], i0, i1);
        wmma::store_matrix_sync(Sbuf + qr * 72 + dc,      o[0], 72, wmma::mem_row_major);
        wmma::store_matrix_sync(Sbuf + qr * 72 + dc + 16, o[1], 72, wmma::mem_row_major);
    }
    __syncthreads();
    for (int idx = tid; idx < 64 * 64; idx += 256) {
        int r = idx >> 6;
        int c = idx & 63;
        float v = Sbuf[r * 72 + c];
        __nv_bfloat16 hv = __float2bfloat16(v);
        size_t g = (size_t)(b * S_ + q0 + r) * D_ + h * DK_ + c;
        Oh_g[g] = hv;
        Ol_g[g] = __float2bfloat16(v - __bfloat162float(hv));
    }
}

// ---------------------------------------------------------------------------
// Launch. Inputs: q,k,v,mask,Wq,bq,Wk,bk,Wv,bv,Wo,bo
// ---------------------------------------------------------------------------
extern "C" void kernel_launch(void* const* d_in, const int* in_sizes, int n_in,
                              void* d_out, int out_size)
{
    const float* q    = (const float*)d_in[0];
    const float* k    = (const float*)d_in[1];
    const float* v    = (const float*)d_in[2];
    const float* Wq   = (const float*)d_in[4];
    const float* bq   = (const float*)d_in[5];
    const float* Wk   = (const float*)d_in[6];
    const float* bk   = (const float*)d_in[7];
    const float* Wv   = (const float*)d_in[8];
    const float* bv   = (const float*)d_in[9];
    const float* Wo   = (const float*)d_in[10];
    const float* bo   = (const float*)d_in[11];
    float* out = (float*)d_out;

    __nv_bfloat16 *X1h, *X1l, *X2h, *X2l, *X3h, *X3l;
    __nv_bfloat16 *W1h, *W1l, *W2h, *W2l, *W3h, *W3l;
    __nv_bfloat16 *Qh, *Ql, *Kh, *Kl, *Vh, *Vl;
    cudaGetSymbolAddress((void**)&X1h, g_X1h);
    cudaGetSymbolAddress((void**)&X1l, g_X1l);
    cudaGetSymbolAddress((void**)&X2h, g_X2h);
    cudaGetSymbolAddress((void**)&X2l, g_X2l);
    cudaGetSymbolAddress((void**)&X3h, g_X3h);
    cudaGetSymbolAddress((void**)&X3l, g_X3l);
    cudaGetSymbolAddress((void**)&W1h, g_W1h);
    cudaGetSymbolAddress((void**)&W1l, g_W1l);
    cudaGetSymbolAddress((void**)&W2h, g_W2h);
    cudaGetSymbolAddress((void**)&W2l, g_W2l);
    cudaGetSymbolAddress((void**)&W3h, g_W3h);
    cudaGetSymbolAddress((void**)&W3l, g_W3l);
    cudaGetSymbolAddress((void**)&Qh, g_Qh);
    cudaGetSymbolAddress((void**)&Ql, g_Ql);
    cudaGetSymbolAddress((void**)&Kh, g_Kh);
    cudaGetSymbolAddress((void**)&Kl, g_Kl);
    cudaGetSymbolAddress((void**)&Vh, g_Vh);
    cudaGetSymbolAddress((void**)&Vl, g_Vl);

    cudaFuncSetAttribute(gemm_wmma_kernel,
                         cudaFuncAttributeMaxDynamicSharedMemorySize, SMEM_BYTES);
    cudaFuncSetAttribute(flash_wmma_kernel,
                         cudaFuncAttributeMaxDynamicSharedMemorySize, FLASH_SMEM);

    const int nX4 = M_ * D_ / 4;
    const int nW4 = D_ * D_ / 4;
    dim3 cvtg((nX4 + nW4 + 255) / 256);
    dim3 cvtw((nW4 + 255) / 256);

    // Convert all three projection inputs + weights.
    cvt_merged_kernel<<<cvtg, 256>>>((const float4*)q, X1h, X1l, nX4,
                                     (const float4*)Wq, W1h, W1l, nW4);
    cvt_merged_kernel<<<cvtg, 256>>>((const float4*)k, X2h, X2l, nX4,
                                     (const float4*)Wk, W2h, W2l, nW4);
    cvt_merged_kernel<<<cvtg, 256>>>((const float4*)v, X3h, X3l, nX4,
                                     (const float4*)Wv, W3h, W3l, nW4);

    // Fused Q/K/V projection GEMM (one launch, 768 CTAs).
    GemmSet sq; sq.Xh = X1h; sq.Xl = X1l; sq.Wh = W1h; sq.Wl = W1l;
    sq.bias = bq; sq.Y = out; sq.Yh = Qh; sq.Yl = Ql; sq.split = 1;
    GemmSet sk; sk.Xh = X2h; sk.Xl = X2l; sk.Wh = W2h; sk.Wl = W2l;
    sk.bias = bk; sk.Y = out; sk.Yh = Kh; sk.Yl = Kl; sk.split = 1;
    GemmSet sv; sv.Xh = X3h; sv.Xl = X3l; sv.Wh = W3h; sv.Wl = W3l;
    sv.bias = bv; sv.Y = out; sv.Yh = Vh; sv.Yl = Vl; sv.split = 1;
    dim3 gqkv(D_ / BN, 3 * (M_ / BM));   // (8, 96)
    gemm_wmma_kernel<<<gqkv, 256, SMEM_BYTES>>>(sq, sk, sv, D_, D_);

    // Attention: writes O hi/lo into g_X1h/g_X1l (input of the final GEMM).
    dim3 fgrid(S_ / 64, B_ * H_);
    flash_wmma_kernel<<<fgrid, 256, FLASH_SMEM>>>(Qh, Ql, Kh, Kl, Vh, Vl, X1h, X1l);

    // Output projection: W-only convert, fp32 output.
    cvt_merged_kernel<<<cvtw, 256>>>((const float4*)q, X2h, X2l, 0,
                                     (const float4*)Wo, W1h, W1l, nW4);
    GemmSet so; so.Xh = X1h; so.Xl = X1l; so.Wh = W1h; so.Wl = W1l;
    so.bias = bo; so.Y = out; so.Yh = Qh; so.Yl = Ql; so.split = 0;
    dim3 gout(D_ / BN, M_ / BM);         // (8, 32)
    gemm_wmma_kernel<<<gout, 256, SMEM_BYTES>>>(so, so, so, D_, D_);
}

// round 15
// speedup vs baseline: 1.0221x; 1.0136x over previous
#include <cuda_runtime.h>
#include <cuda_bf16.h>
#include <cuda_pipeline.h>
#include <mma.h>
#include <math.h>

using namespace nvcuda;

// Problem constants
#define B_  2
#define S_  2048
#define D_  1024
#define H_  16
#define DK_ 64
#define M_  (B_*S_)

// GEMM tiling (measured: fused QKV 302.8us, 2 CTAs/SM)
#define BM 128
#define BN 128
#define BK 32
#define LDT 40
#define TILE_ELEMS (BM*LDT)
#define STAGE_ELEMS (4*TILE_ELEMS)
#define SMEM_BYTES (2*STAGE_ELEMS*2)

// Flash smem (bytes): 64 queries, double-buffered KV, P aliased on S, 3 syncs.
#define FQH 0
#define FQL 9216
#define FKV0 18432
#define FKV1 55296
#define FS  92160
#define FST 110592
#define FLASH_SMEM 111360

// Scratch (device globals — no allocation allowed)
__device__ __nv_bfloat16 g_X1h[M_*D_];
__device__ __nv_bfloat16 g_X1l[M_*D_];
__device__ __nv_bfloat16 g_X2h[M_*D_];
__device__ __nv_bfloat16 g_X2l[M_*D_];
__device__ __nv_bfloat16 g_X3h[M_*D_];
__device__ __nv_bfloat16 g_X3l[M_*D_];
__device__ __nv_bfloat16 g_W1h[D_*D_];
__device__ __nv_bfloat16 g_W1l[D_*D_];
__device__ __nv_bfloat16 g_W2h[D_*D_];
__device__ __nv_bfloat16 g_W2l[D_*D_];
__device__ __nv_bfloat16 g_W3h[D_*D_];
__device__ __nv_bfloat16 g_W3l[D_*D_];
__device__ __nv_bfloat16 g_Qh[M_*D_];
__device__ __nv_bfloat16 g_Ql[M_*D_];
__device__ __nv_bfloat16 g_Kh[M_*D_];
__device__ __nv_bfloat16 g_Kl[M_*D_];
__device__ __nv_bfloat16 g_Vh[M_*D_];
__device__ __nv_bfloat16 g_Vl[M_*D_];

struct GemmSet {
    const __nv_bfloat16* Xh;
    const __nv_bfloat16* Xl;
    const __nv_bfloat16* Wh;
    const __nv_bfloat16* Wl;
    const float* bias;
    float* Y;
    __nv_bfloat16* Yh;
    __nv_bfloat16* Yl;
    int split;
};

// ---------------------------------------------------------------------------
// fp32 -> (hi, lo) bf16 split helpers.
// ---------------------------------------------------------------------------
__device__ __forceinline__ void split4(const float4* src, __nv_bfloat16* hi,
                                       __nv_bfloat16* lo, int i)
{
    float4 v = src[i];
    __nv_bfloat16 h0 = __float2bfloat16(v.x);
    __nv_bfloat16 h1 = __float2bfloat16(v.y);
    __nv_bfloat16 h2 = __float2bfloat16(v.z);
    __nv_bfloat16 h3 = __float2bfloat16(v.w);
    __nv_bfloat162 hh0, hh1, ll0, ll1;
    hh0.x = h0; hh0.y = h1; hh1.x = h2; hh1.y = h3;
    ll0.x = __float2bfloat16(v.x - __bfloat162float(h0));
    ll0.y = __float2bfloat16(v.y - __bfloat162float(h1));
    ll1.x = __float2bfloat16(v.z - __bfloat162float(h2));
    ll1.y = __float2bfloat16(v.w - __bfloat162float(h3));
    *(__nv_bfloat162*)&hi[i*4]     = hh0;
    *(__nv_bfloat162*)&hi[i*4 + 2] = hh1;
    *(__nv_bfloat162*)&lo[i*4]     = ll0;
    *(__nv_bfloat162*)&lo[i*4 + 2] = ll1;
}

// Single-launch convert for all three projection inputs + weights.
__global__ __launch_bounds__(256)
void cvt6_kernel(const float4* x1, __nv_bfloat16* x1h, __nv_bfloat16* x1l,
                 const float4* x2, __nv_bfloat16* x2h, __nv_bfloat16* x2l,
                 const float4* x3, __nv_bfloat16* x3h, __nv_bfloat16* x3l,
                 int nx4,
                 const float4* w1, __nv_bfloat16* w1h, __nv_bfloat16* w1l,
                 const float4* w2, __nv_bfloat16* w2h, __nv_bfloat16* w2l,
                 const float4* w3, __nv_bfloat16* w3h, __nv_bfloat16* w3l,
                 int nw4)
{
    int i = blockIdx.x * blockDim.x + threadIdx.x;
    if (i < nx4) {
        split4(x1, x1h, x1l, i);
    } else if (i < 2 * nx4) {
        split4(x2, x2h, x2l, i - nx4);
    } else if (i < 3 * nx4) {
        split4(x3, x3h, x3l, i - 2 * nx4);
    } else {
        int j = i - 3 * nx4;
        if (j < nw4) {
            split4(w1, w1h, w1l, j);
        } else if (j < 2 * nw4) {
            split4(w2, w2h, w2l, j - nw4);
        } else if (j < 3 * nw4) {
            split4(w3, w3h, w3l, j - 2 * nw4);
        }
    }
}

__global__ __launch_bounds__(256)
void cvt_merged_kernel(const float4* __restrict__ x,
                       __nv_bfloat16* __restrict__ xh,
                       __nv_bfloat16* __restrict__ xl,
                       int nx4,
                       const float4* __restrict__ w,
                       __nv_bfloat16* __restrict__ wh,
                       __nv_bfloat16* __restrict__ wl,
                       int nw4)
{
    int i = blockIdx.x * blockDim.x + threadIdx.x;
    if (i < nx4) {
        split4(x, xh, xl, i);
    } else if (i < nx4 + nw4) {
        split4(w, wh, wl, i - nx4);
    }
}

// ---------------------------------------------------------------------------
// Fused GEMM: grid.y selects one of up to 3 (X,W,bias,Y) sets (blockIdx.y>>5).
// ---------------------------------------------------------------------------
__global__ __launch_bounds__(256)
void gemm_wmma_kernel(GemmSet s0, GemmSet s1, GemmSet s2, int N, int K)
{
    extern __shared__ __nv_bfloat16 sm[];
    __shared__ __align__(16) float biasTile[16][136];

    const int tid = threadIdx.x;
    const int wid = tid >> 5;
    const int sel = blockIdx.y >> 5;
    const GemmSet& s = (sel == 0) ? s0 : ((sel == 1) ? s1 : s2);
    const __nv_bfloat16* Xh = s.Xh;
    const __nv_bfloat16* Xl = s.Xl;
    const __nv_bfloat16* Wh = s.Wh;
    const __nv_bfloat16* Wl = s.Wl;

    const int m0  = (blockIdx.y & 31) * BM;
    const int n0  = blockIdx.x * BN;
    const int wm  = (wid & 1) * 64;
    const int wn  = (wid >> 1) * 32;

    for (int idx = tid; idx < 16 * 128; idx += 256) {
        int r = idx >> 7;
        int c = idx & 127;
        biasTile[r][c] = s.bias[n0 + c];
    }
    __syncthreads();

    wmma::fragment<wmma::accumulator, 16, 16, 16, float> acc[4][2];
    for (int mi = 0; mi < 4; mi++)
        for (int ni = 0; ni < 2; ni++)
            wmma::load_matrix_sync(acc[mi][ni], &biasTile[0][wn + ni * 16], 136,
                                   wmma::mem_row_major);

    const int NT = K / BK;

    {
        for (int p = 0; p < 2; p++) {
            int chunk = tid + p * 256;
            int row = chunk >> 2;
            int cc  = chunk & 3;
            const __nv_bfloat16* sa = Xh + (size_t)(m0 + row) * K + cc * 8;
            const __nv_bfloat16* sb = Xl + (size_t)(m0 + row) * K + cc * 8;
            const __nv_bfloat16* sc = Wh + (size_t)(n0 + row) * K + cc * 8;
            const __nv_bfloat16* sd = Wl + (size_t)(n0 + row) * K + cc * 8;
            int so = row * LDT + cc * 8;
            __pipeline_memcpy_async(&sm[so], sa, 16);
            __pipeline_memcpy_async(&sm[TILE_ELEMS + so], sb, 16);
            __pipeline_memcpy_async(&sm[2 * TILE_ELEMS + so], sc, 16);
            __pipeline_memcpy_async(&sm[3 * TILE_ELEMS + so], sd, 16);
        }
        __pipeline_commit();
    }

    for (int t = 0; t < NT; t++) {
        int st = (t & 1) * STAGE_ELEMS;
        if (t + 1 < NT) {
            int k0 = (t + 1) * BK;
            int sn = ((t + 1) & 1) * STAGE_ELEMS;
            for (int p = 0; p < 2; p++) {
                int chunk = tid + p * 256;
                int row = chunk >> 2;
                int cc  = chunk & 3;
                const __nv_bfloat16* sa = Xh + (size_t)(m0 + row) * K + k0 + cc * 8;
                const __nv_bfloat16* sb = Xl + (size_t)(m0 + row) * K + k0 + cc * 8;
                const __nv_bfloat16* sc = Wh + (size_t)(n0 + row) * K + k0 + cc * 8;
                const __nv_bfloat16* sd = Wl + (size_t)(n0 + row) * K + k0 + cc * 8;
                int so = row * LDT + cc * 8;
                __pipeline_memcpy_async(&sm[sn + so], sa, 16);
                __pipeline_memcpy_async(&sm[sn + TILE_ELEMS + so], sb, 16);
                __pipeline_memcpy_async(&sm[sn + 2 * TILE_ELEMS + so], sc, 16);
                __pipeline_memcpy_async(&sm[sn + 3 * TILE_ELEMS + so], sd, 16);
            }
            __pipeline_commit();
            __pipeline_wait_prior(1);
        } else {
            __pipeline_wait_prior(0);
        }
        __syncthreads();

        for (int ks = 0; ks < 2; ks++) {
            int kc = ks * 16;
            wmma::fragment<wmma::matrix_a, 16, 16, 16, __nv_bfloat16, wmma::row_major> ah[4], al[4];
            wmma::fragment<wmma::matrix_b, 16, 16, 16, __nv_bfloat16, wmma::col_major> bh[2], bl[2];
            for (int mi = 0; mi < 4; mi++) {
                int r = wm + mi * 16;
                wmma::load_matrix_sync(ah[mi], &sm[st + r * LDT + kc], LDT);
                wmma::load_matrix_sync(al[mi], &sm[st + TILE_ELEMS + r * LDT + kc], LDT);
            }
            for (int ni = 0; ni < 2; ni++) {
                int r = wn + ni * 16;
                wmma::load_matrix_sync(bh[ni], &sm[st + 2 * TILE_ELEMS + r * LDT + kc], LDT);
                wmma::load_matrix_sync(bl[ni], &sm[st + 3 * TILE_ELEMS + r * LDT + kc], LDT);
            }
            for (int mi = 0; mi < 4; mi++) {
                for (int ni = 0; ni < 2; ni++) {
                    wmma::mma_sync(acc[mi][ni], ah[mi], bh[ni], acc[mi][ni]);
                    wmma::mma_sync(acc[mi][ni], ah[mi], bl[ni], acc[mi][ni]);
                    wmma::mma_sync(acc[mi][ni], al[mi], bh[ni], acc[mi][ni]);
                }
            }
        }
        __syncthreads();
    }

    if (s.split == 0) {
        for (int mi = 0; mi < 4; mi++) {
            for (int ni = 0; ni < 2; ni++) {
                int row = m0 + wm + mi * 16;
                int col = n0 + wn + ni * 16;
                wmma::store_matrix_sync(&s.Y[(size_t)row * N + col], acc[mi][ni], N,
                                        wmma::mem_row_major);
            }
        }
    } else {
        float* stage = (float*)sm;
        for (int mi = 0; mi < 4; mi++)
            for (int ni = 0; ni < 2; ni++)
                wmma::store_matrix_sync(stage + (wm + mi * 16) * 132 + wn + ni * 16,
                                        acc[mi][ni], 132, wmma::mem_row_major);
        __syncthreads();
        for (int idx = tid; idx < 128 * 128; idx += 256) {
            int r = idx >> 7;
            int c = idx & 127;
            float v = stage[r * 132 + c];
            __nv_bfloat16 hv = __float2bfloat16(v);
            size_t g = (size_t)(m0 + r) * N + n0 + c;
            s.Yh[g] = hv;
            s.Yl[g] = __float2bfloat16(v - __bfloat162float(hv));
        }
    }
}

// ---------------------------------------------------------------------------
// Flash v8 = v7 + LPT scheduling: longest CTAs (high qt) launch FIRST.
// ---------------------------------------------------------------------------
__device__ __forceinline__ void flash_load_64(char* dst, const __nv_bfloat16* src,
                                              int rowbase, int h, int tid)
{
    for (int p = 0; p < 2; p++) {
        int idx = tid + p * 256;
        int r = idx >> 3;
        int c = idx & 7;
        const __nv_bfloat16* s = src + (size_t)(rowbase + r) * D_ + h * DK_ + c * 8;
        __pipeline_memcpy_async(dst + r * 144 + c * 16, s, 16);
    }
}

__device__ __forceinline__ void flash_load_kv(char* kv,
                                              const __nv_bfloat16* Kh_g,
                                              const __nv_bfloat16* Kl_g,
                                              const __nv_bfloat16* Vh_g,
                                              const __nv_bfloat16* Vl_g,
                                              int rowbase, int h, int tid)
{
    flash_load_64(kv,         Kh_g, rowbase, h, tid);
    flash_load_64(kv + 9216,  Kl_g, rowbase, h, tid);
    flash_load_64(kv + 18432, Vh_g, rowbase, h, tid);
    flash_load_64(kv + 27648, Vl_g, rowbase, h, tid);
}

__device__ __forceinline__ void scale_frag_rows(
    wmma::fragment<wmma::accumulator, 16, 16, 16, float>& f, float s0, float s1)
{
    f.x[0] *= s0; f.x[1] *= s0; f.x[4] *= s0; f.x[5] *= s0;
    f.x[2] *= s1; f.x[3] *= s1; f.x[6] *= s1; f.x[7] *= s1;
}

__global__ __launch_bounds__(256)
void flash_wmma_kernel(const __nv_bfloat16* __restrict__ Qh_g,
                       const __nv_bfloat16* __restrict__ Ql_g,
                       const __nv_bfloat16* __restrict__ Kh_g,
                       const __nv_bfloat16* __restrict__ Kl_g,
                       const __nv_bfloat16* __restrict__ Vh_g,
                       const __nv_bfloat16* __restrict__ Vl_g,
                       __nv_bfloat16* __restrict__ Oh_g,
                       __nv_bfloat16* __restrict__ Ol_g)
{
    extern __shared__ char smb[];

    const int tid  = threadIdx.x;
    const int wid  = tid >> 5;
    const int lane = tid & 31;
    // LPT: highest qt (most tiles) scheduled first -> minimal tail.
    const int qt   = gridDim.x - 1 - blockIdx.x;
    const int bhv  = blockIdx.y;
    const int b    = bhv / H_;
    const int h    = bhv % H_;
    const int q0   = qt * 64;

    float* Sbuf  = (float*)(smb + FS);
    __nv_bfloat16* Pbuf = (__nv_bfloat16*)(smb + FS);
    float* mArr  = (float*)(smb + FST);
    float* lArr  = mArr + 64;
    float* scArr = lArr + 64;

    flash_load_64(smb + FQH, Qh_g, b * S_ + q0, h, tid);
    flash_load_64(smb + FQL, Ql_g, b * S_ + q0, h, tid);
    flash_load_kv(smb + FKV0, Kh_g, Kl_g, Vh_g, Vl_g, b * S_, h, tid);
    __pipeline_commit();

    if (tid < 64) {
        mArr[tid] = -INFINITY;
        lArr[tid] = 0.f;
    }

    const int qr   = (wid & 3) * 16;
    const int dc   = (wid >> 2) * 32;
    const int rowA = qr + (lane >> 2);
    const int rowB = rowA + 8;

    wmma::fragment<wmma::accumulator, 16, 16, 16, float> o[2];
    wmma::fill_fragment(o[0], 0.f);
    wmma::fill_fragment(o[1], 0.f);

    const __nv_bfloat16* Qhs = (const __nv_bfloat16*)(smb + FQH);
    const __nv_bfloat16* Qls = (const __nv_bfloat16*)(smb + FQL);

    const int ntiles = qt + 1;
    for (int kt = 0; kt < ntiles; kt++) {
        __pipeline_wait_prior(0);
        __syncthreads();
        if (kt + 1 < ntiles) {
            flash_load_kv(smb + (((kt + 1) & 1) ? FKV1 : FKV0),
                          Kh_g, Kl_g, Vh_g, Vl_g, b * S_ + (kt + 1) * 64, h, tid);
            __pipeline_commit();
        }

        const char* kv = smb + ((kt & 1) ? FKV1 : FKV0);
        const __nv_bfloat16* Khs = (const __nv_bfloat16*)kv;
        const __nv_bfloat16* Kls = (const __nv_bfloat16*)(kv + 9216);
        const __nv_bfloat16* Vhs = (const __nv_bfloat16*)(kv + 18432);
        const __nv_bfloat16* Vls = (const __nv_bfloat16*)(kv + 27648);

        // ---- S = Q K^T ----
        {
            wmma::fragment<wmma::accumulator, 16, 16, 16, float> s[2];
            wmma::fill_fragment(s[0], 0.f);
            wmma::fill_fragment(s[1], 0.f);
            for (int ks = 0; ks < 4; ks++) {
                int kc = ks * 16;
                wmma::fragment<wmma::matrix_a, 16, 16, 16, __nv_bfloat16, wmma::row_major> qh, ql;
                wmma::load_matrix_sync(qh, Qhs + qr * 72 + kc, 72);
                wmma::load_matrix_sync(ql, Qls + qr * 72 + kc, 72);
                for (int ni = 0; ni < 2; ni++) {
                    wmma::fragment<wmma::matrix_b, 16, 16, 16, __nv_bfloat16, wmma::col_major> kh, kl;
                    wmma::load_matrix_sync(kh, Khs + (dc + ni * 16) * 72 + kc, 72);
                    wmma::load_matrix_sync(kl, Kls + (dc + ni * 16) * 72 + kc, 72);
                    wmma::mma_sync(s[ni], qh, kh, s[ni]);
                    wmma::mma_sync(s[ni], qh, kl, s[ni]);
                    wmma::mma_sync(s[ni], ql, kh, s[ni]);
                }
            }
            wmma::store_matrix_sync(Sbuf + qr * 72 + dc,      s[0], 72, wmma::mem_row_major);
            wmma::store_matrix_sync(Sbuf + qr * 72 + dc + 16, s[1], 72, wmma::mem_row_major);
        }
        __syncthreads();

        // ---- online softmax; P overwrites S ----
        {
            const int r  = tid >> 2;
            const int sub = tid & 3;
            const int cb = sub * 16;
            const int kb = kt * 64;
            float* Srow = Sbuf + r * 72 + cb;
            float vals[16];
            float mx = -INFINITY;
            for (int i = 0; i < 16; i++) {
                float v = Srow[i] * 0.125f;
                if (kb + cb + i > q0 + r) v = -1e9f;
                vals[i] = v;
                mx = fmaxf(mx, v);
            }
            mx = fmaxf(mx, __shfl_xor_sync(0xffffffffu, mx, 1));
            mx = fmaxf(mx, __shfl_xor_sync(0xffffffffu, mx, 2));
            float mold = mArr[r];
            float mnew = fmaxf(mold, mx);
            float sum = 0.f;
            __nv_bfloat16* Ph = Pbuf + r * 144;
            __nv_bfloat16* Pl = Ph + 72;
            for (int i = 0; i < 16; i += 2) {
                float p0 = __expf(vals[i] - mnew);
                float p1 = __expf(vals[i + 1] - mnew);
                sum += p0 + p1;
                __nv_bfloat16 h0 = __float2bfloat16(p0);
                __nv_bfloat16 h1 = __float2bfloat16(p1);
                __nv_bfloat162 hh, ll;
                hh.x = h0; hh.y = h1;
                ll.x = __float2bfloat16(p0 - __bfloat162float(h0));
                ll.y = __float2bfloat16(p1 - __bfloat162float(h1));
                *(__nv_bfloat162*)&Ph[cb + i] = hh;
                *(__nv_bfloat162*)&Pl[cb + i] = ll;
            }
            sum += __shfl_xor_sync(0xffffffffu, sum, 1);
            sum += __shfl_xor_sync(0xffffffffu, sum, 2);
            float sc = __expf(mold - mnew);
            if (sub == 0) {
                mArr[r] = mnew;
                lArr[r] = lArr[r] * sc + sum;
                scArr[r] = sc;
            }
        }
        __syncthreads();

        // ---- rescale O in registers, then O += P V ----
        {
            float s0 = scArr[rowA];
            float s1 = scArr[rowB];
            scale_frag_rows(o[0], s0, s1);
            scale_frag_rows(o[1], s0, s1);
            for (int ks = 0; ks < 4; ks++) {
                int kc = ks * 16;
                wmma::fragment<wmma::matrix_a, 16, 16, 16, __nv_bfloat16, wmma::row_major> ph, pl;
                wmma::load_matrix_sync(ph, Pbuf + qr * 144 + kc, 144);
                wmma::load_matrix_sync(pl, Pbuf + qr * 144 + 72 + kc, 144);
                for (int ni = 0; ni < 2; ni++) {
                    wmma::fragment<wmma::matrix_b, 16, 16, 16, __nv_bfloat16, wmma::row_major> vh, vl;
                    wmma::load_matrix_sync(vh, Vhs + kc * 72 + dc + ni * 16, 72);
                    wmma::load_matrix_sync(vl, Vls + kc * 72 + dc + ni * 16, 72);
                    wmma::mma_sync(o[ni], ph, vh, o[ni]);
                    wmma::mma_sync(o[ni], ph, vl, o[ni]);
                    wmma::mma_sync(o[ni], pl, vh, o[ni]);
                }
            }
        }
    }

    // ---- epilogue ----
    __syncthreads();
    {
        float i0 = 1.f / lArr[rowA];
        float i1 = 1.f / lArr[rowB];
        scale_frag_rows(o[0], i0, i1);
        scale_frag_rows(o[1], i0, i1);
        wmma::store_matrix_sync(Sbuf + qr * 72 + dc,      o[0], 72, wmma::mem_row_major);
        wmma::store_matrix_sync(Sbuf + qr * 72 + dc + 16, o[1], 72, wmma::mem_row_major);
    }
    __syncthreads();
    for (int idx = tid; idx < 64 * 64; idx += 256) {
        int r = idx >> 6;
        int c = idx & 63;
        float v = Sbuf[r * 72 + c];
        __nv_bfloat16 hv = __float2bfloat16(v);
        size_t g = (size_t)(b * S_ + q0 + r) * D_ + h * DK_ + c;
        Oh_g[g] = hv;
        Ol_g[g] = __float2bfloat16(v - __bfloat162float(hv));
    }
}

// ---------------------------------------------------------------------------
// Launch. Inputs: q,k,v,mask,Wq,bq,Wk,bk,Wv,bv,Wo,bo
// ---------------------------------------------------------------------------
extern "C" void kernel_launch(void* const* d_in, const int* in_sizes, int n_in,
                              void* d_out, int out_size)
{
    const float* q    = (const float*)d_in[0];
    const float* k    = (const float*)d_in[1];
    const float* v    = (const float*)d_in[2];
    const float* Wq   = (const float*)d_in[4];
    const float* bq   = (const float*)d_in[5];
    const float* Wk   = (const float*)d_in[6];
    const float* bk   = (const float*)d_in[7];
    const float* Wv   = (const float*)d_in[8];
    const float* bv   = (const float*)d_in[9];
    const float* Wo   = (const float*)d_in[10];
    const float* bo   = (const float*)d_in[11];
    float* out = (float*)d_out;

    __nv_bfloat16 *X1h, *X1l, *X2h, *X2l, *X3h, *X3l;
    __nv_bfloat16 *W1h, *W1l, *W2h, *W2l, *W3h, *W3l;
    __nv_bfloat16 *Qh, *Ql, *Kh, *Kl, *Vh, *Vl;
    cudaGetSymbolAddress((void**)&X1h, g_X1h);
    cudaGetSymbolAddress((void**)&X1l, g_X1l);
    cudaGetSymbolAddress((void**)&X2h, g_X2h);
    cudaGetSymbolAddress((void**)&X2l, g_X2l);
    cudaGetSymbolAddress((void**)&X3h, g_X3h);
    cudaGetSymbolAddress((void**)&X3l, g_X3l);
    cudaGetSymbolAddress((void**)&W1h, g_W1h);
    cudaGetSymbolAddress((void**)&W1l, g_W1l);
    cudaGetSymbolAddress((void**)&W2h, g_W2h);
    cudaGetSymbolAddress((void**)&W2l, g_W2l);
    cudaGetSymbolAddress((void**)&W3h, g_W3h);
    cudaGetSymbolAddress((void**)&W3l, g_W3l);
    cudaGetSymbolAddress((void**)&Qh, g_Qh);
    cudaGetSymbolAddress((void**)&Ql, g_Ql);
    cudaGetSymbolAddress((void**)&Kh, g_Kh);
    cudaGetSymbolAddress((void**)&Kl, g_Kl);
    cudaGetSymbolAddress((void**)&Vh, g_Vh);
    cudaGetSymbolAddress((void**)&Vl, g_Vl);

    cudaFuncSetAttribute(gemm_wmma_kernel,
                         cudaFuncAttributeMaxDynamicSharedMemorySize, SMEM_BYTES);
    cudaFuncSetAttribute(flash_wmma_kernel,
                         cudaFuncAttributeMaxDynamicSharedMemorySize, FLASH_SMEM);

    const int nX4 = M_ * D_ / 4;
    const int nW4 = D_ * D_ / 4;
    dim3 cvt6g((3 * nX4 + 3 * nW4 + 255) / 256);
    dim3 cvtw((nW4 + 255) / 256);

    // One launch converts q,k,v inputs + Wq,Wk,Wv weights.
    cvt6_kernel<<<cvt6g, 256>>>(
        (const float4*)q, X1h, X1l,
        (const float4*)k, X2h, X2l,
        (const float4*)v, X3h, X3l, nX4,
        (const float4*)Wq, W1h, W1l,
        (const float4*)Wk, W2h, W2l,
        (const float4*)Wv, W3h, W3l, nW4);

    // Fused Q/K/V projection GEMM (one launch, 768 CTAs).
    GemmSet sq; sq.Xh = X1h; sq.Xl = X1l; sq.Wh = W1h; sq.Wl = W1l;
    sq.bias = bq; sq.Y = out; sq.Yh = Qh; sq.Yl = Ql; sq.split = 1;
    GemmSet sk; sk.Xh = X2h; sk.Xl = X2l; sk.Wh = W2h; sk.Wl = W2l;
    sk.bias = bk; sk.Y = out; sk.Yh = Kh; sk.Yl = Kl; sk.split = 1;
    GemmSet sv; sv.Xh = X3h; sv.Xl = X3l; sv.Wh = W3h; sv.Wl = W3l;
    sv.bias = bv; sv.Y = out; sv.Yh = Vh; sv.Yl = Vl; sv.split = 1;
    dim3 gqkv(D_ / BN, 3 * (M_ / BM));   // (8, 96)
    gemm_wmma_kernel<<<gqkv, 256, SMEM_BYTES>>>(sq, sk, sv, D_, D_);

    // Attention (LPT-ordered): writes O hi/lo into g_X1h/g_X1l.
    dim3 fgrid(S_ / 64, B_ * H_);
    flash_wmma_kernel<<<fgrid, 256, FLASH_SMEM>>>(Qh, Ql, Kh, Kl, Vh, Vl, X1h, X1l);

    // Output projection: W-only convert, fp32 output.
    cvt_merged_kernel<<<cvtw, 256>>>((const float4*)q, X2h, X2l, 0,
                                     (const float4*)Wo, W1h, W1l, nW4);
    GemmSet so; so.Xh = X1h; so.Xl = X1l; so.Wh = W1h; so.Wl = W1l;
    so.bias = bo; so.Y = out; so.Yh = Qh; so.Yl = Ql; so.split = 0;
    dim3 gout(D_ / BN, M_ / BM);         // (8, 32)
    gemm_wmma_kernel<<<gout, 256, SMEM_BYTES>>>(so, so, so, D_, D_);
}

// round 16
// speedup vs baseline: 1.0424x; 1.0198x over previous
#include <cuda_runtime.h>
#include <cuda_bf16.h>
#include <cuda_pipeline.h>
#include <mma.h>
#include <math.h>

using namespace nvcuda;

// Problem constants
#define B_  2
#define S_  2048
#define D_  1024
#define H_  16
#define DK_ 64
#define M_  (B_*S_)

// GEMM tiling (at the HMMA.16816 throughput ceiling: ~103us/GEMM, 2 CTAs/SM)
#define BM 128
#define BN 128
#define BK 32
#define LDT 40
#define TILE_ELEMS (BM*LDT)
#define STAGE_ELEMS (4*TILE_ELEMS)
#define SMEM_BYTES (2*STAGE_ELEMS*2)

// Flash v9 smem (bytes): 64 queries, double-buffered KV, in-register softmax.
// P (bf16 hi/lo, stride 144) lives where S used to; S never touches smem.
#define FQH 0
#define FQL 9216
#define FKV0 18432
#define FKV1 55296
#define FS  92160            // P region / epilogue O staging (18432 B)
#define FST 110592           // m[64], l[64], pmax[2][64], psum[2][64]
#define FLASH_SMEM 112128

// Scratch (device globals — no allocation allowed)
__device__ __nv_bfloat16 g_X1h[M_*D_];
__device__ __nv_bfloat16 g_X1l[M_*D_];
__device__ __nv_bfloat16 g_X2h[M_*D_];
__device__ __nv_bfloat16 g_X2l[M_*D_];
__device__ __nv_bfloat16 g_X3h[M_*D_];
__device__ __nv_bfloat16 g_X3l[M_*D_];
__device__ __nv_bfloat16 g_W1h[D_*D_];
__device__ __nv_bfloat16 g_W1l[D_*D_];
__device__ __nv_bfloat16 g_W2h[D_*D_];
__device__ __nv_bfloat16 g_W2l[D_*D_];
__device__ __nv_bfloat16 g_W3h[D_*D_];
__device__ __nv_bfloat16 g_W3l[D_*D_];
__device__ __nv_bfloat16 g_W4h[D_*D_];
__device__ __nv_bfloat16 g_W4l[D_*D_];
__device__ __nv_bfloat16 g_Qh[M_*D_];
__device__ __nv_bfloat16 g_Ql[M_*D_];
__device__ __nv_bfloat16 g_Kh[M_*D_];
__device__ __nv_bfloat16 g_Kl[M_*D_];
__device__ __nv_bfloat16 g_Vh[M_*D_];
__device__ __nv_bfloat16 g_Vl[M_*D_];

struct GemmSet {
    const __nv_bfloat16* Xh;
    const __nv_bfloat16* Xl;
    const __nv_bfloat16* Wh;
    const __nv_bfloat16* Wl;
    const float* bias;
    float* Y;
    __nv_bfloat16* Yh;
    __nv_bfloat16* Yl;
    int split;
};

// ---------------------------------------------------------------------------
// fp32 -> (hi, lo) bf16 split helpers.
// ---------------------------------------------------------------------------
__device__ __forceinline__ void split4(const float4* src, __nv_bfloat16* hi,
                                       __nv_bfloat16* lo, int i)
{
    float4 v = src[i];
    __nv_bfloat16 h0 = __float2bfloat16(v.x);
    __nv_bfloat16 h1 = __float2bfloat16(v.y);
    __nv_bfloat16 h2 = __float2bfloat16(v.z);
    __nv_bfloat16 h3 = __float2bfloat16(v.w);
    __nv_bfloat162 hh0, hh1, ll0, ll1;
    hh0.x = h0; hh0.y = h1; hh1.x = h2; hh1.y = h3;
    ll0.x = __float2bfloat16(v.x - __bfloat162float(h0));
    ll0.y = __float2bfloat16(v.y - __bfloat162float(h1));
    ll1.x = __float2bfloat16(v.z - __bfloat162float(h2));
    ll1.y = __float2bfloat16(v.w - __bfloat162float(h3));
    *(__nv_bfloat162*)&hi[i*4]     = hh0;
    *(__nv_bfloat162*)&hi[i*4 + 2] = hh1;
    *(__nv_bfloat162*)&lo[i*4]     = ll0;
    *(__nv_bfloat162*)&lo[i*4 + 2] = ll1;
}

// Single launch: converts q,k,v inputs + all four weight matrices.
__global__ __launch_bounds__(256)
void cvt8_kernel(const float4* x1, __nv_bfloat16* x1h, __nv_bfloat16* x1l,
                 const float4* x2, __nv_bfloat16* x2h, __nv_bfloat16* x2l,
                 const float4* x3, __nv_bfloat16* x3h, __nv_bfloat16* x3l,
                 int nx4,
                 const float4* w1, __nv_bfloat16* w1h, __nv_bfloat16* w1l,
                 const float4* w2, __nv_bfloat16* w2h, __nv_bfloat16* w2l,
                 const float4* w3, __nv_bfloat16* w3h, __nv_bfloat16* w3l,
                 const float4* w4, __nv_bfloat16* w4h, __nv_bfloat16* w4l,
                 int nw4)
{
    int i = blockIdx.x * blockDim.x + threadIdx.x;
    if (i < nx4) {
        split4(x1, x1h, x1l, i);
    } else if (i < 2 * nx4) {
        split4(x2, x2h, x2l, i - nx4);
    } else if (i < 3 * nx4) {
        split4(x3, x3h, x3l, i - 2 * nx4);
    } else {
        int j = i - 3 * nx4;
        if (j < nw4) {
            split4(w1, w1h, w1l, j);
        } else if (j < 2 * nw4) {
            split4(w2, w2h, w2l, j - nw4);
        } else if (j < 3 * nw4) {
            split4(w3, w3h, w3l, j - 2 * nw4);
        } else if (j < 4 * nw4) {
            split4(w4, w4h, w4l, j - 3 * nw4);
        }
    }
}

// ---------------------------------------------------------------------------
// Fused GEMM: grid.y selects one of up to 3 (X,W,bias,Y) sets (blockIdx.y>>5).
// ---------------------------------------------------------------------------
__global__ __launch_bounds__(256)
void gemm_wmma_kernel(GemmSet s0, GemmSet s1, GemmSet s2, int N, int K)
{
    extern __shared__ __nv_bfloat16 sm[];
    __shared__ __align__(16) float biasTile[16][136];

    const int tid = threadIdx.x;
    const int wid = tid >> 5;
    const int sel = blockIdx.y >> 5;
    const GemmSet& s = (sel == 0) ? s0 : ((sel == 1) ? s1 : s2);
    const __nv_bfloat16* Xh = s.Xh;
    const __nv_bfloat16* Xl = s.Xl;
    const __nv_bfloat16* Wh = s.Wh;
    const __nv_bfloat16* Wl = s.Wl;

    const int m0  = (blockIdx.y & 31) * BM;
    const int n0  = blockIdx.x * BN;
    const int wm  = (wid & 1) * 64;
    const int wn  = (wid >> 1) * 32;

    for (int idx = tid; idx < 16 * 128; idx += 256) {
        int r = idx >> 7;
        int c = idx & 127;
        biasTile[r][c] = s.bias[n0 + c];
    }
    __syncthreads();

    wmma::fragment<wmma::accumulator, 16, 16, 16, float> acc[4][2];
    for (int mi = 0; mi < 4; mi++)
        for (int ni = 0; ni < 2; ni++)
            wmma::load_matrix_sync(acc[mi][ni], &biasTile[0][wn + ni * 16], 136,
                                   wmma::mem_row_major);

    const int NT = K / BK;

    {
        for (int p = 0; p < 2; p++) {
            int chunk = tid + p * 256;
            int row = chunk >> 2;
            int cc  = chunk & 3;
            const __nv_bfloat16* sa = Xh + (size_t)(m0 + row) * K + cc * 8;
            const __nv_bfloat16* sb = Xl + (size_t)(m0 + row) * K + cc * 8;
            const __nv_bfloat16* sc = Wh + (size_t)(n0 + row) * K + cc * 8;
            const __nv_bfloat16* sd = Wl + (size_t)(n0 + row) * K + cc * 8;
            int so = row * LDT + cc * 8;
            __pipeline_memcpy_async(&sm[so], sa, 16);
            __pipeline_memcpy_async(&sm[TILE_ELEMS + so], sb, 16);
            __pipeline_memcpy_async(&sm[2 * TILE_ELEMS + so], sc, 16);
            __pipeline_memcpy_async(&sm[3 * TILE_ELEMS + so], sd, 16);
        }
        __pipeline_commit();
    }

    for (int t = 0; t < NT; t++) {
        int st = (t & 1) * STAGE_ELEMS;
        if (t + 1 < NT) {
            int k0 = (t + 1) * BK;
            int sn = ((t + 1) & 1) * STAGE_ELEMS;
            for (int p = 0; p < 2; p++) {
                int chunk = tid + p * 256;
                int row = chunk >> 2;
                int cc  = chunk & 3;
                const __nv_bfloat16* sa = Xh + (size_t)(m0 + row) * K + k0 + cc * 8;
                const __nv_bfloat16* sb = Xl + (size_t)(m0 + row) * K + k0 + cc * 8;
                const __nv_bfloat16* sc = Wh + (size_t)(n0 + row) * K + k0 + cc * 8;
                const __nv_bfloat16* sd = Wl + (size_t)(n0 + row) * K + k0 + cc * 8;
                int so = row * LDT + cc * 8;
                __pipeline_memcpy_async(&sm[sn + so], sa, 16);
                __pipeline_memcpy_async(&sm[sn + TILE_ELEMS + so], sb, 16);
                __pipeline_memcpy_async(&sm[sn + 2 * TILE_ELEMS + so], sc, 16);
                __pipeline_memcpy_async(&sm[sn + 3 * TILE_ELEMS + so], sd, 16);
            }
            __pipeline_commit();
            __pipeline_wait_prior(1);
        } else {
            __pipeline_wait_prior(0);
        }
        __syncthreads();

        for (int ks = 0; ks < 2; ks++) {
            int kc = ks * 16;
            wmma::fragment<wmma::matrix_a, 16, 16, 16, __nv_bfloat16, wmma::row_major> ah[4], al[4];
            wmma::fragment<wmma::matrix_b, 16, 16, 16, __nv_bfloat16, wmma::col_major> bh[2], bl[2];
            for (int mi = 0; mi < 4; mi++) {
                int r = wm + mi * 16;
                wmma::load_matrix_sync(ah[mi], &sm[st + r * LDT + kc], LDT);
                wmma::load_matrix_sync(al[mi], &sm[st + TILE_ELEMS + r * LDT + kc], LDT);
            }
            for (int ni = 0; ni < 2; ni++) {
                int r = wn + ni * 16;
                wmma::load_matrix_sync(bh[ni], &sm[st + 2 * TILE_ELEMS + r * LDT + kc], LDT);
                wmma::load_matrix_sync(bl[ni], &sm[st + 3 * TILE_ELEMS + r * LDT + kc], LDT);
            }
            for (int mi = 0; mi < 4; mi++) {
                for (int ni = 0; ni < 2; ni++) {
                    wmma::mma_sync(acc[mi][ni], ah[mi], bh[ni], acc[mi][ni]);
                    wmma::mma_sync(acc[mi][ni], ah[mi], bl[ni], acc[mi][ni]);
                    wmma::mma_sync(acc[mi][ni], al[mi], bh[ni], acc[mi][ni]);
                }
            }
        }
        __syncthreads();
    }

    if (s.split == 0) {
        for (int mi = 0; mi < 4; mi++) {
            for (int ni = 0; ni < 2; ni++) {
                int row = m0 + wm + mi * 16;
                int col = n0 + wn + ni * 16;
                wmma::store_matrix_sync(&s.Y[(size_t)row * N + col], acc[mi][ni], N,
                                        wmma::mem_row_major);
            }
        }
    } else {
        float* stage = (float*)sm;
        for (int mi = 0; mi < 4; mi++)
            for (int ni = 0; ni < 2; ni++)
                wmma::store_matrix_sync(stage + (wm + mi * 16) * 132 + wn + ni * 16,
                                        acc[mi][ni], 132, wmma::mem_row_major);
        __syncthreads();
        for (int idx = tid; idx < 128 * 128; idx += 256) {
            int r = idx >> 7;
            int c = idx & 127;
            float v = stage[r * 132 + c];
            __nv_bfloat16 hv = __float2bfloat16(v);
            size_t g = (size_t)(m0 + r) * N + n0 + c;
            s.Yh[g] = hv;
            s.Yl[g] = __float2bfloat16(v - __bfloat162float(hv));
        }
    }
}

// ---------------------------------------------------------------------------
// Flash v9: in-REGISTER softmax on the QK accumulator fragments.
// f32 acc element map (sm_80+, rows validated R11):
//   rows: {0,1,4,5} -> lane/4 ; {2,3,6,7} -> lane/4+8
//   cols: (lane&3)*2 + (e&1) + 8*((e>>2)&1)
// Only per-row max/sum scalars cross warps via smem; S never hits smem.
// ---------------------------------------------------------------------------
__device__ __forceinline__ void flash_load_64(char* dst, const __nv_bfloat16* src,
                                              int rowbase, int h, int tid)
{
    for (int p = 0; p < 2; p++) {
        int idx = tid + p * 256;
        int r = idx >> 3;
        int c = idx & 7;
        const __nv_bfloat16* s = src + (size_t)(rowbase + r) * D_ + h * DK_ + c * 8;
        __pipeline_memcpy_async(dst + r * 144 + c * 16, s, 16);
    }
}

__device__ __forceinline__ void flash_load_kv(char* kv,
                                              const __nv_bfloat16* Kh_g,
                                              const __nv_bfloat16* Kl_g,
                                              const __nv_bfloat16* Vh_g,
                                              const __nv_bfloat16* Vl_g,
                                              int rowbase, int h, int tid)
{
    flash_load_64(kv,         Kh_g, rowbase, h, tid);
    flash_load_64(kv + 9216,  Kl_g, rowbase, h, tid);
    flash_load_64(kv + 18432, Vh_g, rowbase, h, tid);
    flash_load_64(kv + 27648, Vl_g, rowbase, h, tid);
}

__device__ __forceinline__ void scale_frag_rows(
    wmma::fragment<wmma::accumulator, 16, 16, 16, float>& f, float s0, float s1)
{
    f.x[0] *= s0; f.x[1] *= s0; f.x[4] *= s0; f.x[5] *= s0;
    f.x[2] *= s1; f.x[3] *= s1; f.x[6] *= s1; f.x[7] *= s1;
}

__device__ __forceinline__ void store_p2(__nv_bfloat16* Ph, int off, float a, float b)
{
    __nv_bfloat16 ha = __float2bfloat16(a);
    __nv_bfloat16 hb = __float2bfloat16(b);
    __nv_bfloat162 hh, ll;
    hh.x = ha; hh.y = hb;
    ll.x = __float2bfloat16(a - __bfloat162float(ha));
    ll.y = __float2bfloat16(b - __bfloat162float(hb));
    *(__nv_bfloat162*)&Ph[off] = hh;          // hi at col
    *(__nv_bfloat162*)&Ph[off + 72] = ll;     // lo at col+72 (same row)
}

__global__ __launch_bounds__(256)
void flash_wmma_kernel(const __nv_bfloat16* __restrict__ Qh_g,
                       const __nv_bfloat16* __restrict__ Ql_g,
                       const __nv_bfloat16* __restrict__ Kh_g,
                       const __nv_bfloat16* __restrict__ Kl_g,
                       const __nv_bfloat16* __restrict__ Vh_g,
                       const __nv_bfloat16* __restrict__ Vl_g,
                       __nv_bfloat16* __restrict__ Oh_g,
                       __nv_bfloat16* __restrict__ Ol_g)
{
    extern __shared__ char smb[];

    const int tid  = threadIdx.x;
    const int wid  = tid >> 5;
    const int lane = tid & 31;
    const int qt   = gridDim.x - 1 - blockIdx.x;   // LPT
    const int bhv  = blockIdx.y;
    const int b    = bhv / H_;
    const int h    = bhv % H_;
    const int q0   = qt * 64;

    float* Obuf = (float*)(smb + FS);              // epilogue staging
    __nv_bfloat16* Pbuf = (__nv_bfloat16*)(smb + FS);
    float* mArr = (float*)(smb + FST);
    float* lArr = mArr + 64;
    float* pmax = lArr + 64;      // [2][64]
    float* psum = pmax + 128;     // [2][64]

    flash_load_64(smb + FQH, Qh_g, b * S_ + q0, h, tid);
    flash_load_64(smb + FQL, Ql_g, b * S_ + q0, h, tid);
    flash_load_kv(smb + FKV0, Kh_g, Kl_g, Vh_g, Vl_g, b * S_, h, tid);
    __pipeline_commit();

    if (tid < 64) {
        mArr[tid] = -INFINITY;
        lArr[tid] = 0.f;
    }

    const int qr   = (wid & 3) * 16;
    const int dc   = (wid >> 2) * 32;
    const int wc   = wid >> 2;
    const int rowA = qr + (lane >> 2);
    const int rowB = rowA + 8;
    const int c2   = (lane & 3) * 2;

    wmma::fragment<wmma::accumulator, 16, 16, 16, float> o[2];
    wmma::fill_fragment(o[0], 0.f);
    wmma::fill_fragment(o[1], 0.f);

    const __nv_bfloat16* Qhs = (const __nv_bfloat16*)(smb + FQH);
    const __nv_bfloat16* Qls = (const __nv_bfloat16*)(smb + FQL);

    const int ntiles = qt + 1;
    for (int kt = 0; kt < ntiles; kt++) {
        __pipeline_wait_prior(0);
        __syncthreads();                 // (B) KV(kt) visible; prev iter retired
        if (kt + 1 < ntiles) {
            flash_load_kv(smb + (((kt + 1) & 1) ? FKV1 : FKV0),
                          Kh_g, Kl_g, Vh_g, Vl_g, b * S_ + (kt + 1) * 64, h, tid);
            __pipeline_commit();
        }

        const char* kv = smb + ((kt & 1) ? FKV1 : FKV0);
        const __nv_bfloat16* Khs = (const __nv_bfloat16*)kv;
        const __nv_bfloat16* Kls = (const __nv_bfloat16*)(kv + 9216);
        const __nv_bfloat16* Vhs = (const __nv_bfloat16*)(kv + 18432);
        const __nv_bfloat16* Vls = (const __nv_bfloat16*)(kv + 27648);

        // ---- S = Q K^T (stays in registers) ----
        wmma::fragment<wmma::accumulator, 16, 16, 16, float> s[2];
        wmma::fill_fragment(s[0], 0.f);
        wmma::fill_fragment(s[1], 0.f);
        for (int ks = 0; ks < 4; ks++) {
            int kc = ks * 16;
            wmma::fragment<wmma::matrix_a, 16, 16, 16, __nv_bfloat16, wmma::row_major> qh, ql;
            wmma::load_matrix_sync(qh, Qhs + qr * 72 + kc, 72);
            wmma::load_matrix_sync(ql, Qls + qr * 72 + kc, 72);
            for (int ni = 0; ni < 2; ni++) {
                wmma::fragment<wmma::matrix_b, 16, 16, 16, __nv_bfloat16, wmma::col_major> kh, kl;
                wmma::load_matrix_sync(kh, Khs + (dc + ni * 16) * 72 + kc, 72);
                wmma::load_matrix_sync(kl, Kls + (dc + ni * 16) * 72 + kc, 72);
                wmma::mma_sync(s[ni], qh, kh, s[ni]);
                wmma::mma_sync(s[ni], qh, kl, s[ni]);
                wmma::mma_sync(s[ni], ql, kh, s[ni]);
            }
        }

        // ---- in-register mask + scale + per-row partial max ----
        const int cgA = q0 + rowA;
        const int cgB = q0 + rowB;
        const int colb = kt * 64 + dc + c2;
        float mxA = -INFINITY, mxB = -INFINITY;
        for (int ni = 0; ni < 2; ni++) {
            int cb = colb + ni * 16;
            float t;
            t = s[ni].x[0] * 0.125f; if (cb     > cgA) t = -1e9f; s[ni].x[0] = t; mxA = fmaxf(mxA, t);
            t = s[ni].x[1] * 0.125f; if (cb + 1 > cgA) t = -1e9f; s[ni].x[1] = t; mxA = fmaxf(mxA, t);
            t = s[ni].x[4] * 0.125f; if (cb + 8 > cgA) t = -1e9f; s[ni].x[4] = t; mxA = fmaxf(mxA, t);
            t = s[ni].x[5] * 0.125f; if (cb + 9 > cgA) t = -1e9f; s[ni].x[5] = t; mxA = fmaxf(mxA, t);
            t = s[ni].x[2] * 0.125f; if (cb     > cgB) t = -1e9f; s[ni].x[2] = t; mxB = fmaxf(mxB, t);
            t = s[ni].x[3] * 0.125f; if (cb + 1 > cgB) t = -1e9f; s[ni].x[3] = t; mxB = fmaxf(mxB, t);
            t = s[ni].x[6] * 0.125f; if (cb + 8 > cgB) t = -1e9f; s[ni].x[6] = t; mxB = fmaxf(mxB, t);
            t = s[ni].x[7] * 0.125f; if (cb + 9 > cgB) t = -1e9f; s[ni].x[7] = t; mxB = fmaxf(mxB, t);
        }
        mxA = fmaxf(mxA, __shfl_xor_sync(0xffffffffu, mxA, 1));
        mxA = fmaxf(mxA, __shfl_xor_sync(0xffffffffu, mxA, 2));
        mxB = fmaxf(mxB, __shfl_xor_sync(0xffffffffu, mxB, 1));
        mxB = fmaxf(mxB, __shfl_xor_sync(0xffffffffu, mxB, 2));
        if ((lane & 3) == 0) {
            pmax[wc * 64 + rowA] = mxA;
            pmax[wc * 64 + rowB] = mxB;
        }
        __syncthreads();                 // (1) pmax ready

        float moldA = mArr[rowA];
        float moldB = mArr[rowB];
        float mnewA = fmaxf(moldA, fmaxf(pmax[rowA], pmax[64 + rowA]));
        float mnewB = fmaxf(moldB, fmaxf(pmax[rowB], pmax[64 + rowB]));
        float scA = __expf(moldA - mnewA);
        float scB = __expf(moldB - mnewB);

        // ---- exp in registers, P (hi/lo bf16) to smem, partial sums ----
        float sumA = 0.f, sumB = 0.f;
        for (int ni = 0; ni < 2; ni++) {
            float p0 = __expf(s[ni].x[0] - mnewA);
            float p1 = __expf(s[ni].x[1] - mnewA);
            float p4 = __expf(s[ni].x[4] - mnewA);
            float p5 = __expf(s[ni].x[5] - mnewA);
            float p2 = __expf(s[ni].x[2] - mnewB);
            float p3 = __expf(s[ni].x[3] - mnewB);
            float p6 = __expf(s[ni].x[6] - mnewB);
            float p7 = __expf(s[ni].x[7] - mnewB);
            sumA += (p0 + p1) + (p4 + p5);
            sumB += (p2 + p3) + (p6 + p7);
            int cl = dc + ni * 16 + c2;
            store_p2(Pbuf + rowA * 144, cl,     p0, p1);
            store_p2(Pbuf + rowA * 144, cl + 8, p4, p5);
            store_p2(Pbuf + rowB * 144, cl,     p2, p3);
            store_p2(Pbuf + rowB * 144, cl + 8, p6, p7);
        }
        sumA += __shfl_xor_sync(0xffffffffu, sumA, 1);
        sumA += __shfl_xor_sync(0xffffffffu, sumA, 2);
        sumB += __shfl_xor_sync(0xffffffffu, sumB, 1);
        sumB += __shfl_xor_sync(0xffffffffu, sumB, 2);
        if ((lane & 3) == 0) {
            psum[wc * 64 + rowA] = sumA;
            psum[wc * 64 + rowB] = sumB;
        }
        __syncthreads();                 // (2) P + psum ready

        if (wc == 0 && (lane & 3) == 0) {
            lArr[rowA] = lArr[rowA] * scA + psum[rowA] + psum[64 + rowA];
            lArr[rowB] = lArr[rowB] * scB + psum[rowB] + psum[64 + rowB];
            mArr[rowA] = mnewA;
            mArr[rowB] = mnewB;
        }

        // ---- rescale O in registers, then O += P V ----
        scale_frag_rows(o[0], scA, scB);
        scale_frag_rows(o[1], scA, scB);
        for (int ks = 0; ks < 4; ks++) {
            int kc = ks * 16;
            wmma::fragment<wmma::matrix_a, 16, 16, 16, __nv_bfloat16, wmma::row_major> ph, pl;
            wmma::load_matrix_sync(ph, Pbuf + qr * 144 + kc, 144);
            wmma::load_matrix_sync(pl, Pbuf + qr * 144 + 72 + kc, 144);
            for (int ni = 0; ni < 2; ni++) {
                wmma::fragment<wmma::matrix_b, 16, 16, 16, __nv_bfloat16, wmma::row_major> vh, vl;
                wmma::load_matrix_sync(vh, Vhs + kc * 72 + dc + ni * 16, 72);
                wmma::load_matrix_sync(vl, Vls + kc * 72 + dc + ni * 16, 72);
                wmma::mma_sync(o[ni], ph, vh, o[ni]);
                wmma::mma_sync(o[ni], ph, vl, o[ni]);
                wmma::mma_sync(o[ni], pl, vh, o[ni]);
            }
        }
    }

    // ---- epilogue: normalize, stage, split to hi/lo bf16 global ----
    __syncthreads();
    {
        float i0 = 1.f / lArr[rowA];
        float i1 = 1.f / lArr[rowB];
        scale_frag_rows(o[0], i0, i1);
        scale_frag_rows(o[1], i0, i1);
        wmma::store_matrix_sync(Obuf + qr * 72 + dc,      o[0], 72, wmma::mem_row_major);
        wmma::store_matrix_sync(Obuf + qr * 72 + dc + 16, o[1], 72, wmma::mem_row_major);
    }
    __syncthreads();
    for (int idx = tid; idx < 64 * 64; idx += 256) {
        int r = idx >> 6;
        int c = idx & 63;
        float v = Obuf[r * 72 + c];
        __nv_bfloat16 hv = __float2bfloat16(v);
        size_t g = (size_t)(b * S_ + q0 + r) * D_ + h * DK_ + c;
        Oh_g[g] = hv;
        Ol_g[g] = __float2bfloat16(v - __bfloat162float(hv));
    }
}

// ---------------------------------------------------------------------------
// Launch. Inputs: q,k,v,mask,Wq,bq,Wk,bk,Wv,bv,Wo,bo
// ---------------------------------------------------------------------------
extern "C" void kernel_launch(void* const* d_in, const int* in_sizes, int n_in,
                              void* d_out, int out_size)
{
    const float* q    = (const float*)d_in[0];
    const float* k    = (const float*)d_in[1];
    const float* v    = (const float*)d_in[2];
    const float* Wq   = (const float*)d_in[4];
    const float* bq   = (const float*)d_in[5];
    const float* Wk   = (const float*)d_in[6];
    const float* bk   = (const float*)d_in[7];
    const float* Wv   = (const float*)d_in[8];
    const float* bv   = (const float*)d_in[9];
    const float* Wo   = (const float*)d_in[10];
    const float* bo   = (const float*)d_in[11];
    float* out = (float*)d_out;

    __nv_bfloat16 *X1h, *X1l, *X2h, *X2l, *X3h, *X3l;
    __nv_bfloat16 *W1h, *W1l, *W2h, *W2l, *W3h, *W3l, *W4h, *W4l;
    __nv_bfloat16 *Qh, *Ql, *Kh, *Kl, *Vh, *Vl;
    cudaGetSymbolAddress((void**)&X1h, g_X1h);
    cudaGetSymbolAddress((void**)&X1l, g_X1l);
    cudaGetSymbolAddress((void**)&X2h, g_X2h);
    cudaGetSymbolAddress((void**)&X2l, g_X2l);
    cudaGetSymbolAddress((void**)&X3h, g_X3h);
    cudaGetSymbolAddress((void**)&X3l, g_X3l);
    cudaGetSymbolAddress((void**)&W1h, g_W1h);
    cudaGetSymbolAddress((void**)&W1l, g_W1l);
    cudaGetSymbolAddress((void**)&W2h, g_W2h);
    cudaGetSymbolAddress((void**)&W2l, g_W2l);
    cudaGetSymbolAddress((void**)&W3h, g_W3h);
    cudaGetSymbolAddress((void**)&W3l, g_W3l);
    cudaGetSymbolAddress((void**)&W4h, g_W4h);
    cudaGetSymbolAddress((void**)&W4l, g_W4l);
    cudaGetSymbolAddress((void**)&Qh, g_Qh);
    cudaGetSymbolAddress((void**)&Ql, g_Ql);
    cudaGetSymbolAddress((void**)&Kh, g_Kh);
    cudaGetSymbolAddress((void**)&Kl, g_Kl);
    cudaGetSymbolAddress((void**)&Vh, g_Vh);
    cudaGetSymbolAddress((void**)&Vl, g_Vl);

    cudaFuncSetAttribute(gemm_wmma_kernel,
                         cudaFuncAttributeMaxDynamicSharedMemorySize, SMEM_BYTES);
    cudaFuncSetAttribute(flash_wmma_kernel,
                         cudaFuncAttributeMaxDynamicSharedMemorySize, FLASH_SMEM);

    const int nX4 = M_ * D_ / 4;
    const int nW4 = D_ * D_ / 4;
    dim3 cvt8g((3 * nX4 + 4 * nW4 + 255) / 256);

    // One launch converts q,k,v inputs + Wq,Wk,Wv,Wo weights.
    cvt8_kernel<<<cvt8g, 256>>>(
        (const float4*)q, X1h, X1l,
        (const float4*)k, X2h, X2l,
        (const float4*)v, X3h, X3l, nX4,
        (const float4*)Wq, W1h, W1l,
        (const float4*)Wk, W2h, W2l,
        (const float4*)Wv, W3h, W3l,
        (const float4*)Wo, W4h, W4l, nW4);

    // Fused Q/K/V projection GEMM (one launch, 768 CTAs).
    GemmSet sq; sq.Xh = X1h; sq.Xl = X1l; sq.Wh = W1h; sq.Wl = W1l;
    sq.bias = bq; sq.Y = out; sq.Yh = Qh; sq.Yl = Ql; sq.split = 1;
    GemmSet sk; sk.Xh = X2h; sk.Xl = X2l; sk.Wh = W2h; sk.Wl = W2l;
    sk.bias = bk; sk.Y = out; sk.Yh = Kh; sk.Yl = Kl; sk.split = 1;
    GemmSet sv; sv.Xh = X3h; sv.Xl = X3l; sv.Wh = W3h; sv.Wl = W3l;
    sv.bias = bv; sv.Y = out; sv.Yh = Vh; sv.Yl = Vl; sv.split = 1;
    dim3 gqkv(D_ / BN, 3 * (M_ / BM));   // (8, 96)
    gemm_wmma_kernel<<<gqkv, 256, SMEM_BYTES>>>(sq, sk, sv, D_, D_);

    // Attention (LPT, in-register softmax): O hi/lo into g_X1h/g_X1l.
    dim3 fgrid(S_ / 64, B_ * H_);
    flash_wmma_kernel<<<fgrid, 256, FLASH_SMEM>>>(Qh, Ql, Kh, Kl, Vh, Vl, X1h, X1l);

    // Output projection: fp32 output (weights pre-converted in cvt8).
    GemmSet so; so.Xh = X1h; so.Xl = X1l; so.Wh = W4h; so.Wl = W4l;
    so.bias = bo; so.Y = out; so.Yh = Qh; so.Yl = Ql; so.split = 0;
    dim3 gout(D_ / BN, M_ / BM);         // (8, 32)
    gemm_wmma_kernel<<<gout, 256, SMEM_BYTES>>>(so, so, so, D_, D_);
}